// round 1
// baseline (speedup 1.0000x reference)
#include <cuda_runtime.h>
#include <math.h>
#include <stdint.h>

#define NNODES 50000
#define NEDGES 800000
#define TOTE   (NEDGES + NNODES)
#define GNUM   64
#define NEG_SLOPE 0.2f

// ---------------- static device scratch (no runtime allocation) ----------------
static __device__ int   g_is64;
static __device__ int   g_src[NEDGES];
static __device__ int   g_dst[NEDGES];
static __device__ int   g_batch[NNODES];
static __device__ int   g_deg[NNODES];
static __device__ int   g_row[NNODES + 1];
static __device__ int   g_cur[NNODES];
static __device__ int   g_col[TOTE];
static __device__ int   g_gptr[GNUM + 1];
static __device__ float g_h[(size_t)NNODES * 256];
static __device__ float g_asrc[NNODES * 4];
static __device__ float g_adst[NNODES * 4];
static __device__ float g_out1[(size_t)NNODES * 64];
static __device__ float g_out2[(size_t)NNODES * 64];
static __device__ float g_gate[NNODES];
static __device__ float g_pooled[GNUM * 64];
static __device__ float g_den[GNUM];

// ---------------- dtype detection (int64 vs int32 edge indices) ----------------
__global__ void detect_kernel(const long long* __restrict__ ei) {
    int lane = threadIdx.x;
    long long v = ei[lane];
    int ok = (v >= 0 && v < (long long)NNODES);
    unsigned all = __all_sync(0xFFFFFFFFu, ok);
    if (lane == 0) g_is64 = all ? 1 : 0;
}

__global__ void convert_kernel(const void* __restrict__ ei, const void* __restrict__ bt,
                               int E, int N) {
    int i = blockIdx.x * blockDim.x + threadIdx.x;
    int total = 2 * E + N;
    if (i >= total) return;
    int is64 = g_is64;
    if (i < 2 * E) {
        int v = is64 ? (int)((const long long*)ei)[i] : ((const int*)ei)[i];
        if (i < E) g_src[i] = v; else g_dst[i - E] = v;
    } else {
        int j = i - 2 * E;
        int v = is64 ? (int)((const long long*)bt)[j] : ((const int*)bt)[j];
        g_batch[j] = v;
    }
}

// ---------------- CSR build ----------------
__global__ void init_kernel(int N) {
    int i = blockIdx.x * blockDim.x + threadIdx.x;
    if (i < N) g_deg[i] = 1;  // self-loop
}

__global__ void degree_kernel(int E) {
    int i = blockIdx.x * blockDim.x + threadIdx.x;
    if (i < E) atomicAdd(&g_deg[g_dst[i]], 1);
}

__global__ void __launch_bounds__(1024) scan_kernel(int N) {
    __shared__ int wsum[32];
    __shared__ int carry;
    int tid = threadIdx.x, lane = tid & 31, wid = tid >> 5;
    if (tid == 0) carry = 0;
    __syncthreads();
    for (int base = 0; base < N; base += 1024) {
        int i = base + tid;
        int x = (i < N) ? g_deg[i] : 0;
        int v = x;
        #pragma unroll
        for (int o = 1; o < 32; o <<= 1) {
            int t = __shfl_up_sync(0xFFFFFFFFu, v, o);
            if (lane >= o) v += t;
        }
        if (lane == 31) wsum[wid] = v;
        __syncthreads();
        if (wid == 0) {
            int w = wsum[lane];
            #pragma unroll
            for (int o = 1; o < 32; o <<= 1) {
                int t = __shfl_up_sync(0xFFFFFFFFu, w, o);
                if (lane >= o) w += t;
            }
            wsum[lane] = w;
        }
        __syncthreads();
        int pre = carry + (wid ? wsum[wid - 1] : 0);
        int excl = pre + v - x;
        if (i < N) { g_row[i] = excl; g_cur[i] = excl; }
        int total = wsum[31];
        __syncthreads();
        if (tid == 0) carry += total;
        __syncthreads();
    }
    if (tid == 0) g_row[N] = carry;
}

__global__ void scatter_kernel(int E, int N) {
    int i = blockIdx.x * blockDim.x + threadIdx.x;
    if (i >= E + N) return;
    int s, d;
    if (i < E) { s = g_src[i]; d = g_dst[i]; }
    else       { s = d = i - E; }
    int pos = atomicAdd(&g_cur[d], 1);
    g_col[pos] = s;
}

// ---------------- SGEMM: C[M,N] = A[M,K] @ B[K,N], fp32, BM=BN=128, BK=8 ----------------
__global__ void __launch_bounds__(256) sgemm_kernel(const float* __restrict__ A,
                                                    const float* __restrict__ B,
                                                    float* __restrict__ C,
                                                    int M, int N, int K) {
    __shared__ float As[8][128];
    __shared__ float Bs[8][128];
    int tid = threadIdx.x;
    int bx = blockIdx.x;   // N tiles
    int by = blockIdx.y;   // M tiles
    int tx = tid & 15, ty = tid >> 4;
    int aRow = tid >> 1;
    int aCol = (tid & 1) * 4;
    int bRow = tid >> 5;
    int bCol = (tid & 31) * 4;
    float acc[8][8];
    #pragma unroll
    for (int i = 0; i < 8; i++)
        #pragma unroll
        for (int j = 0; j < 8; j++) acc[i][j] = 0.f;

    const float* Aptr = A + (size_t)(by * 128) * K;
    const float* Bptr = B + bx * 128;
    int gRow = by * 128 + aRow;

    for (int k0 = 0; k0 < K; k0 += 8) {
        float4 av = make_float4(0.f, 0.f, 0.f, 0.f);
        if (gRow < M) av = *(const float4*)(Aptr + (size_t)aRow * K + k0 + aCol);
        As[aCol + 0][aRow] = av.x;
        As[aCol + 1][aRow] = av.y;
        As[aCol + 2][aRow] = av.z;
        As[aCol + 3][aRow] = av.w;
        float4 bv = *(const float4*)(Bptr + (size_t)(k0 + bRow) * N + bCol);
        *(float4*)&Bs[bRow][bCol] = bv;
        __syncthreads();
        #pragma unroll
        for (int k = 0; k < 8; k++) {
            float ra[8], rb[8];
            #pragma unroll
            for (int i = 0; i < 8; i++) ra[i] = As[k][ty * 8 + i];
            #pragma unroll
            for (int j = 0; j < 8; j++) rb[j] = Bs[k][tx * 8 + j];
            #pragma unroll
            for (int i = 0; i < 8; i++)
                #pragma unroll
                for (int j = 0; j < 8; j++) acc[i][j] += ra[i] * rb[j];
        }
        __syncthreads();
    }
    #pragma unroll
    for (int i = 0; i < 8; i++) {
        int row = by * 128 + ty * 8 + i;
        if (row >= M) continue;
        float* cp = C + (size_t)row * N + bx * 128 + tx * 8;
        *(float4*)(cp + 0) = make_float4(acc[i][0], acc[i][1], acc[i][2], acc[i][3]);
        *(float4*)(cp + 4) = make_float4(acc[i][4], acc[i][5], acc[i][6], acc[i][7]);
    }
}

// ---------------- attention scores: asrc[v,h] = sum_c h[v,h,c]*a_src[h,c] ----------------
__global__ void __launch_bounds__(256) attn_kernel(const float* __restrict__ h,
                                                   const float* __restrict__ att_src,
                                                   const float* __restrict__ att_dst,
                                                   float* __restrict__ asrc,
                                                   float* __restrict__ adst, int N) {
    int warp = (blockIdx.x * blockDim.x + threadIdx.x) >> 5;
    if (warp >= N) return;
    int lane = threadIdx.x & 31;
    #pragma unroll
    for (int hd = 0; hd < 4; hd++) {
        float hv0 = h[(size_t)warp * 256 + hd * 64 + lane];
        float hv1 = h[(size_t)warp * 256 + hd * 64 + lane + 32];
        float s = hv0 * att_src[hd * 64 + lane] + hv1 * att_src[hd * 64 + lane + 32];
        float d = hv0 * att_dst[hd * 64 + lane] + hv1 * att_dst[hd * 64 + lane + 32];
        #pragma unroll
        for (int o = 16; o; o >>= 1) {
            s += __shfl_xor_sync(0xFFFFFFFFu, s, o);
            d += __shfl_xor_sync(0xFFFFFFFFu, d, o);
        }
        if (lane == 0) { asrc[warp * 4 + hd] = s; adst[warp * 4 + hd] = d; }
    }
}

// ---------------- GAT aggregation: warp per destination node, atomic-free ----------------
__global__ void __launch_bounds__(256) aggregate_kernel(const float* __restrict__ h,
                                                        const float* __restrict__ asrc,
                                                        const float* __restrict__ adst,
                                                        const float* __restrict__ bias,
                                                        float* __restrict__ out, int N) {
    int warp = (blockIdx.x * blockDim.x + threadIdx.x) >> 5;
    if (warp >= N) return;
    int lane = threadIdx.x & 31;
    int start = g_row[warp], end = g_row[warp + 1];
    float4 ad = *(const float4*)(adst + 4 * warp);

    // pass 1: per-head max over incoming edges
    float m0 = -1e30f, m1 = -1e30f, m2 = -1e30f, m3 = -1e30f;
    for (int j = start + lane; j < end; j += 32) {
        int s = g_col[j];
        float4 as = *(const float4*)(asrc + 4 * s);
        float e0 = as.x + ad.x; e0 = (e0 > 0.f) ? e0 : NEG_SLOPE * e0;
        float e1 = as.y + ad.y; e1 = (e1 > 0.f) ? e1 : NEG_SLOPE * e1;
        float e2 = as.z + ad.z; e2 = (e2 > 0.f) ? e2 : NEG_SLOPE * e2;
        float e3 = as.w + ad.w; e3 = (e3 > 0.f) ? e3 : NEG_SLOPE * e3;
        m0 = fmaxf(m0, e0); m1 = fmaxf(m1, e1); m2 = fmaxf(m2, e2); m3 = fmaxf(m3, e3);
    }
    #pragma unroll
    for (int o = 16; o; o >>= 1) {
        m0 = fmaxf(m0, __shfl_xor_sync(0xFFFFFFFFu, m0, o));
        m1 = fmaxf(m1, __shfl_xor_sync(0xFFFFFFFFu, m1, o));
        m2 = fmaxf(m2, __shfl_xor_sync(0xFFFFFFFFu, m2, o));
        m3 = fmaxf(m3, __shfl_xor_sync(0xFFFFFFFFu, m3, o));
    }
    int head = lane >> 3;  // lane covers channels [lane*8, lane*8+8) -> head = lane/8
    float mh  = (head == 0) ? m0 : (head == 1) ? m1 : (head == 2) ? m2 : m3;
    float adh = (head == 0) ? ad.x : (head == 1) ? ad.y : (head == 2) ? ad.z : ad.w;

    // pass 2: exp, denominator, and weighted feature sum (warp lanes over 256 channels)
    float4 A0 = make_float4(0.f, 0.f, 0.f, 0.f);
    float4 A1 = make_float4(0.f, 0.f, 0.f, 0.f);
    float den = 0.f;
    const float4* hb = (const float4*)h;
    for (int j = start; j < end; ++j) {
        int s = g_col[j];                                   // broadcast load
        float4 as = *(const float4*)(asrc + 4 * s);         // broadcast load
        float e = ((head == 0) ? as.x : (head == 1) ? as.y : (head == 2) ? as.z : as.w) + adh;
        e = (e > 0.f) ? e : NEG_SLOPE * e;
        float wgt = expf(e - mh);
        den += wgt;
        const float4* hp = hb + (size_t)s * 64 + lane * 2;  // 1KB coalesced gather per edge
        float4 v0 = hp[0];
        float4 v1 = hp[1];
        A0.x += wgt * v0.x; A0.y += wgt * v0.y; A0.z += wgt * v0.z; A0.w += wgt * v0.w;
        A1.x += wgt * v1.x; A1.y += wgt * v1.y; A1.z += wgt * v1.z; A1.w += wgt * v1.w;
    }
    float inv = 1.f / (den + 1e-16f);
    float r[8] = {A0.x * inv, A0.y * inv, A0.z * inv, A0.w * inv,
                  A1.x * inv, A1.y * inv, A1.z * inv, A1.w * inv};
    // mean over heads: butterfly over lane bits 3,4
    #pragma unroll
    for (int k = 0; k < 8; ++k) {
        r[k] += __shfl_xor_sync(0xFFFFFFFFu, r[k], 8);
        r[k] += __shfl_xor_sync(0xFFFFFFFFu, r[k], 16);
    }
    if (lane < 8) {
        float o_[8];
        #pragma unroll
        for (int k = 0; k < 8; ++k) {
            float v = 0.25f * r[k] + bias[lane * 8 + k];
            o_[k] = 1.f / (1.f + expf(-v));
        }
        float4* op = (float4*)(out + (size_t)warp * 64 + lane * 8);
        op[0] = make_float4(o_[0], o_[1], o_[2], o_[3]);
        op[1] = make_float4(o_[4], o_[5], o_[6], o_[7]);
    }
}

// ---------------- gate scalar: g[v] = relu(bn(out2@gw1+gb1)) @ gw2 + gb2 ----------------
__global__ void __launch_bounds__(64) gate_kernel(const float* __restrict__ x,
                                                  const float* __restrict__ gw1,
                                                  const float* __restrict__ gb1,
                                                  const float* __restrict__ gamma,
                                                  const float* __restrict__ beta,
                                                  const float* __restrict__ gw2,
                                                  const float* __restrict__ gb2,
                                                  float* __restrict__ gout, int N) {
    __shared__ float sW[64 * 64];
    __shared__ float sX[64 * 65];  // padded to avoid bank conflicts
    int tid = threadIdx.x;
    int vbase = blockIdx.x * 64;
    for (int i = tid; i < 4096; i += 64) sW[i] = gw1[i];
    for (int i = tid; i < 4096; i += 64) {
        int r = i >> 6, c = i & 63;
        int v = vbase + r;
        sX[r * 65 + c] = (v < N) ? x[(size_t)v * 64 + c] : 0.f;
    }
    __syncthreads();
    int v = vbase + tid;
    if (v >= N) return;
    float acc[64];
    #pragma unroll
    for (int j = 0; j < 64; ++j) acc[j] = 0.f;
    for (int c = 0; c < 64; ++c) {
        float xv = sX[tid * 65 + c];
        #pragma unroll
        for (int j = 0; j < 64; ++j) acc[j] += xv * sW[c * 64 + j];
    }
    float kinv = rsqrtf(1.0f + 1e-5f);
    float s = 0.f;
    #pragma unroll
    for (int j = 0; j < 64; ++j) {
        float t = (acc[j] + gb1[j]) * kinv * gamma[j] + beta[j];
        t = fmaxf(t, 0.f);
        s += t * gw2[j];
    }
    gout[v] = s + gb2[0];
}

// ---------------- per-graph boundaries (batch is sorted) ----------------
__global__ void gptr_kernel(int N) {
    int v = blockIdx.x * blockDim.x + threadIdx.x;
    if (v >= N) return;
    int b = g_batch[v];
    if (v == 0) {
        for (int i = 0; i <= b; i++) g_gptr[i] = 0;
    } else {
        int bp = g_batch[v - 1];
        for (int i = bp + 1; i <= b; i++) g_gptr[i] = v;
    }
    if (v == N - 1) {
        for (int i = b + 1; i <= GNUM; i++) g_gptr[i] = N;
    }
}

// ---------------- pooling: one block per graph, atomic-free ----------------
__global__ void __launch_bounds__(256) pool_kernel(const float* __restrict__ out2, int N) {
    int b = blockIdx.x;
    int start = g_gptr[b], end = g_gptr[b + 1];
    __shared__ float smax[256];
    __shared__ float sacc[256];
    __shared__ float sden[4];
    int tid = threadIdx.x;
    float m = -1e30f;
    for (int v = start + tid; v < end; v += 256) m = fmaxf(m, g_gate[v]);
    smax[tid] = m;
    __syncthreads();
    for (int s = 128; s; s >>= 1) {
        if (tid < s) smax[tid] = fmaxf(smax[tid], smax[tid + s]);
        __syncthreads();
    }
    float mx = smax[0];
    __syncthreads();
    int c = tid & 63;
    int sub = tid >> 6;
    float acc = 0.f, dacc = 0.f;
    for (int v = start + sub; v < end; v += 4) {
        float w = expf(g_gate[v] - mx);
        acc += w * out2[(size_t)v * 64 + c];
        if (c == 0) dacc += w;
    }
    sacc[tid] = acc;
    if (c == 0) sden[sub] = dacc;
    __syncthreads();
    if (sub == 0) g_pooled[b * 64 + c] = sacc[c] + sacc[64 + c] + sacc[128 + c] + sacc[192 + c];
    if (tid == 0) g_den[b] = sden[0] + sden[1] + sden[2] + sden[3];
}

__global__ void final_kernel(const float* __restrict__ lw, const float* __restrict__ lb,
                             float* __restrict__ out) {
    int g = threadIdx.x;
    if (g >= GNUM) return;
    float s = 0.f;
    for (int c = 0; c < 64; c++) s += g_pooled[g * 64 + c] * lw[c];
    s = s / (g_den[g] + 1e-16f) + lb[0];
    out[g] = 1.f / (1.f + expf(-s));
}

// ---------------- launch ----------------
extern "C" void kernel_launch(void* const* d_in, const int* in_sizes, int n_in,
                              void* d_out, int out_size) {
    const float* x  = (const float*)d_in[0];
    const void*  ei = d_in[1];
    const void*  bt = d_in[2];
    // num_graphs may or may not be materialized as an input (scalar, size 1)
    int o = (in_sizes[3] == 1) ? 1 : 0;
    const float* W1  = (const float*)d_in[3 + o];
    const float* as1 = (const float*)d_in[4 + o];
    const float* ad1 = (const float*)d_in[5 + o];
    const float* b1  = (const float*)d_in[6 + o];
    const float* W2  = (const float*)d_in[7 + o];
    const float* as2 = (const float*)d_in[8 + o];
    const float* ad2 = (const float*)d_in[9 + o];
    const float* b2  = (const float*)d_in[10 + o];
    const float* gw1 = (const float*)d_in[11 + o];
    const float* gb1 = (const float*)d_in[12 + o];
    const float* gam = (const float*)d_in[13 + o];
    const float* bet = (const float*)d_in[14 + o];
    const float* gw2 = (const float*)d_in[15 + o];
    const float* gb2 = (const float*)d_in[16 + o];
    const float* lw  = (const float*)d_in[17 + o];
    const float* lb  = (const float*)d_in[18 + o];

    int N = in_sizes[0] / 128;
    int E = in_sizes[1] / 2;

    float *hbuf, *asrcb, *adstb, *out1b, *out2b, *gateb;
    cudaGetSymbolAddress((void**)&hbuf,  g_h);
    cudaGetSymbolAddress((void**)&asrcb, g_asrc);
    cudaGetSymbolAddress((void**)&adstb, g_adst);
    cudaGetSymbolAddress((void**)&out1b, g_out1);
    cudaGetSymbolAddress((void**)&out2b, g_out2);
    cudaGetSymbolAddress((void**)&gateb, g_gate);

    // index normalization + CSR build
    detect_kernel<<<1, 32>>>((const long long*)ei);
    int convT = 2 * E + N;
    convert_kernel<<<(convT + 255) / 256, 256>>>(ei, bt, E, N);
    init_kernel<<<(N + 255) / 256, 256>>>(N);
    degree_kernel<<<(E + 255) / 256, 256>>>(E);
    scan_kernel<<<1, 1024>>>(N);
    scatter_kernel<<<(E + N + 255) / 256, 256>>>(E, N);

    dim3 ggrid(2, (N + 127) / 128);
    int wblocks = (N + 7) / 8;

    // layer 1
    sgemm_kernel<<<ggrid, 256>>>(x, W1, hbuf, N, 256, 128);
    attn_kernel<<<wblocks, 256>>>(hbuf, as1, ad1, asrcb, adstb, N);
    aggregate_kernel<<<wblocks, 256>>>(hbuf, asrcb, adstb, b1, out1b, N);

    // layer 2
    sgemm_kernel<<<ggrid, 256>>>(out1b, W2, hbuf, N, 256, 64);
    attn_kernel<<<wblocks, 256>>>(hbuf, as2, ad2, asrcb, adstb, N);
    aggregate_kernel<<<wblocks, 256>>>(hbuf, asrcb, adstb, b2, out2b, N);

    // pooling
    gate_kernel<<<(N + 63) / 64, 64>>>(out2b, gw1, gb1, gam, bet, gw2, gb2, gateb, N);
    gptr_kernel<<<(N + 255) / 256, 256>>>(N);
    pool_kernel<<<GNUM, 256>>>(out2b, N);
    final_kernel<<<1, 64>>>(lw, lb, (float*)d_out);
}

// round 2
// speedup vs baseline: 1.1199x; 1.1199x over previous
#include <cuda_runtime.h>
#include <cuda_fp16.h>
#include <math.h>
#include <stdint.h>

#define NNODES 50000
#define NEDGES 800000
#define TOTE   (NEDGES + NNODES)
#define GNUM   64
#define NEG_SLOPE 0.2f

// ---------------- static device scratch (no runtime allocation) ----------------
static __device__ int   g_is64;
static __device__ int   g_src[NEDGES];
static __device__ int   g_dst[NEDGES];
static __device__ int   g_batch[NNODES];
static __device__ int   g_deg[NNODES];
static __device__ int   g_row[NNODES + 1];
static __device__ int   g_cur[NNODES];
static __device__ int   g_col[TOTE];
static __device__ int   g_gptr[GNUM + 1];
static __device__ uint4 g_hh[(size_t)NNODES * 32];   // h as fp16: 256 half = 32 uint4 per node
static __device__ float g_asrc[NNODES * 4];
static __device__ float g_adst[NNODES * 4];
static __device__ float g_out1[(size_t)NNODES * 64];
static __device__ float g_out2[(size_t)NNODES * 64];
static __device__ float g_gate[NNODES];
static __device__ float g_pooled[GNUM * 64];
static __device__ float g_den[GNUM];

// ---------------- dtype detection (int64 vs int32 edge indices) ----------------
__global__ void detect_kernel(const long long* __restrict__ ei) {
    int lane = threadIdx.x;
    long long v = ei[lane];
    int ok = (v >= 0 && v < (long long)NNODES);
    unsigned all = __all_sync(0xFFFFFFFFu, ok);
    if (lane == 0) g_is64 = all ? 1 : 0;
}

__global__ void convert_kernel(const void* __restrict__ ei, const void* __restrict__ bt,
                               int E, int N) {
    int i = blockIdx.x * blockDim.x + threadIdx.x;
    int total = 2 * E + N;
    if (i >= total) return;
    int is64 = g_is64;
    if (i < 2 * E) {
        int v = is64 ? (int)((const long long*)ei)[i] : ((const int*)ei)[i];
        if (i < E) g_src[i] = v; else g_dst[i - E] = v;
    } else {
        int j = i - 2 * E;
        int v = is64 ? (int)((const long long*)bt)[j] : ((const int*)bt)[j];
        g_batch[j] = v;
        g_deg[j] = 1;  // self-loop init fused here
    }
}

// ---------------- CSR build ----------------
__global__ void degree_kernel(int E) {
    int i = blockIdx.x * blockDim.x + threadIdx.x;
    if (i < E) atomicAdd(&g_deg[g_dst[i]], 1);
}

__global__ void __launch_bounds__(1024) scan_kernel(int N) {
    __shared__ int wsum[32];
    __shared__ int carry;
    int tid = threadIdx.x, lane = tid & 31, wid = tid >> 5;
    if (tid == 0) carry = 0;
    __syncthreads();
    for (int base = 0; base < N; base += 1024) {
        int i = base + tid;
        int x = (i < N) ? g_deg[i] : 0;
        int v = x;
        #pragma unroll
        for (int o = 1; o < 32; o <<= 1) {
            int t = __shfl_up_sync(0xFFFFFFFFu, v, o);
            if (lane >= o) v += t;
        }
        if (lane == 31) wsum[wid] = v;
        __syncthreads();
        if (wid == 0) {
            int w = wsum[lane];
            #pragma unroll
            for (int o = 1; o < 32; o <<= 1) {
                int t = __shfl_up_sync(0xFFFFFFFFu, w, o);
                if (lane >= o) w += t;
            }
            wsum[lane] = w;
        }
        __syncthreads();
        int pre = carry + (wid ? wsum[wid - 1] : 0);
        int excl = pre + v - x;
        if (i < N) { g_row[i] = excl; g_cur[i] = excl; }
        int total = wsum[31];
        __syncthreads();
        if (tid == 0) carry += total;
        __syncthreads();
    }
    if (tid == 0) g_row[N] = carry;
}

__global__ void scatter_kernel(int E, int N) {
    int i = blockIdx.x * blockDim.x + threadIdx.x;
    if (i >= E + N) return;
    int s, d;
    if (i < E) { s = g_src[i]; d = g_dst[i]; }
    else       { s = d = i - E; }
    int pos = atomicAdd(&g_cur[d], 1);
    g_col[pos] = s;
}

// ---------------- SGEMM: half C[M,256] = A[M,K] @ B[K,256], BM=BN=128, BK=8 ----------------
__global__ void __launch_bounds__(256) sgemm_half_kernel(const float* __restrict__ A,
                                                         const float* __restrict__ B,
                                                         __half* __restrict__ C,
                                                         int M, int K) {
    const int N = 256;
    __shared__ float As[8][128];
    __shared__ float Bs[8][128];
    int tid = threadIdx.x;
    int bx = blockIdx.x;   // N tiles (2)
    int by = blockIdx.y;   // M tiles
    int tx = tid & 15, ty = tid >> 4;
    int aRow = tid >> 1;
    int aCol = (tid & 1) * 4;
    int bRow = tid >> 5;
    int bCol = (tid & 31) * 4;
    float acc[8][8];
    #pragma unroll
    for (int i = 0; i < 8; i++)
        #pragma unroll
        for (int j = 0; j < 8; j++) acc[i][j] = 0.f;

    const float* Aptr = A + (size_t)(by * 128) * K;
    const float* Bptr = B + bx * 128;
    int gRow = by * 128 + aRow;

    for (int k0 = 0; k0 < K; k0 += 8) {
        float4 av = make_float4(0.f, 0.f, 0.f, 0.f);
        if (gRow < M) av = *(const float4*)(Aptr + (size_t)aRow * K + k0 + aCol);
        As[aCol + 0][aRow] = av.x;
        As[aCol + 1][aRow] = av.y;
        As[aCol + 2][aRow] = av.z;
        As[aCol + 3][aRow] = av.w;
        float4 bv = *(const float4*)(Bptr + (size_t)(k0 + bRow) * N + bCol);
        *(float4*)&Bs[bRow][bCol] = bv;
        __syncthreads();
        #pragma unroll
        for (int k = 0; k < 8; k++) {
            float ra[8], rb[8];
            #pragma unroll
            for (int i = 0; i < 8; i++) ra[i] = As[k][ty * 8 + i];
            #pragma unroll
            for (int j = 0; j < 8; j++) rb[j] = Bs[k][tx * 8 + j];
            #pragma unroll
            for (int i = 0; i < 8; i++)
                #pragma unroll
                for (int j = 0; j < 8; j++) acc[i][j] += ra[i] * rb[j];
        }
        __syncthreads();
    }
    #pragma unroll
    for (int i = 0; i < 8; i++) {
        int row = by * 128 + ty * 8 + i;
        if (row >= M) continue;
        __half h8[8];
        #pragma unroll
        for (int j = 0; j < 8; j++) h8[j] = __float2half(acc[i][j]);
        *(uint4*)(C + (size_t)row * N + bx * 128 + tx * 8) = *(uint4*)h8;
    }
}

// ---------------- attention scores from fp16 h ----------------
__global__ void __launch_bounds__(256) attn_kernel(const __half* __restrict__ h,
                                                   const float* __restrict__ att_src,
                                                   const float* __restrict__ att_dst,
                                                   float* __restrict__ asrc,
                                                   float* __restrict__ adst, int N) {
    int warp = (blockIdx.x * blockDim.x + threadIdx.x) >> 5;
    if (warp >= N) return;
    int lane = threadIdx.x & 31;
    #pragma unroll
    for (int hd = 0; hd < 4; hd++) {
        __half2 hv = *(const __half2*)(h + (size_t)warp * 256 + hd * 64 + 2 * lane);
        float2 f = __half22float2(hv);
        float a0 = att_src[hd * 64 + 2 * lane], a1 = att_src[hd * 64 + 2 * lane + 1];
        float d0 = att_dst[hd * 64 + 2 * lane], d1 = att_dst[hd * 64 + 2 * lane + 1];
        float s = f.x * a0 + f.y * a1;
        float d = f.x * d0 + f.y * d1;
        #pragma unroll
        for (int o = 16; o; o >>= 1) {
            s += __shfl_xor_sync(0xFFFFFFFFu, s, o);
            d += __shfl_xor_sync(0xFFFFFFFFu, d, o);
        }
        if (lane == 0) { asrc[warp * 4 + hd] = s; adst[warp * 4 + hd] = d; }
    }
}

// ---------------- GAT aggregation: warp per destination node, fp16 gather, 2x unrolled ----------------
__device__ __forceinline__ void fma_half8(float* a, uint4 v, float w) {
    __half2* p = (__half2*)&v;
    #pragma unroll
    for (int q = 0; q < 4; q++) {
        float2 f = __half22float2(p[q]);
        a[2 * q]     += w * f.x;
        a[2 * q + 1] += w * f.y;
    }
}

__global__ void __launch_bounds__(256) aggregate_kernel(const uint4* __restrict__ hh,
                                                        const float* __restrict__ asrc,
                                                        const float* __restrict__ adst,
                                                        const float* __restrict__ bias,
                                                        float* __restrict__ out, int N) {
    int warp = (blockIdx.x * blockDim.x + threadIdx.x) >> 5;
    if (warp >= N) return;
    int lane = threadIdx.x & 31;
    int start = g_row[warp], end = g_row[warp + 1];
    float4 ad = *(const float4*)(adst + 4 * warp);

    // pass 1: per-head max over incoming edges
    float m0 = -1e30f, m1 = -1e30f, m2 = -1e30f, m3 = -1e30f;
    for (int j = start + lane; j < end; j += 32) {
        int s = g_col[j];
        float4 as = *(const float4*)(asrc + 4 * s);
        float e0 = as.x + ad.x; e0 = (e0 > 0.f) ? e0 : NEG_SLOPE * e0;
        float e1 = as.y + ad.y; e1 = (e1 > 0.f) ? e1 : NEG_SLOPE * e1;
        float e2 = as.z + ad.z; e2 = (e2 > 0.f) ? e2 : NEG_SLOPE * e2;
        float e3 = as.w + ad.w; e3 = (e3 > 0.f) ? e3 : NEG_SLOPE * e3;
        m0 = fmaxf(m0, e0); m1 = fmaxf(m1, e1); m2 = fmaxf(m2, e2); m3 = fmaxf(m3, e3);
    }
    #pragma unroll
    for (int o = 16; o; o >>= 1) {
        m0 = fmaxf(m0, __shfl_xor_sync(0xFFFFFFFFu, m0, o));
        m1 = fmaxf(m1, __shfl_xor_sync(0xFFFFFFFFu, m1, o));
        m2 = fmaxf(m2, __shfl_xor_sync(0xFFFFFFFFu, m2, o));
        m3 = fmaxf(m3, __shfl_xor_sync(0xFFFFFFFFu, m3, o));
    }
    int head = lane >> 3;  // lane covers channels [lane*8, lane*8+8) -> head = lane/8
    float mh  = (head == 0) ? m0 : (head == 1) ? m1 : (head == 2) ? m2 : m3;
    float adh = (head == 0) ? ad.x : (head == 1) ? ad.y : (head == 2) ? ad.z : ad.w;

    // pass 2: exp, denominator, weighted feature sum; 2 edges in flight per iter
    float a0[8], a1[8];
    #pragma unroll
    for (int k = 0; k < 8; k++) { a0[k] = 0.f; a1[k] = 0.f; }
    float den0 = 0.f, den1 = 0.f;

    int j = start;
    for (; j + 2 <= end; j += 2) {
        int s0 = g_col[j];
        int s1 = g_col[j + 1];
        float4 as0 = *(const float4*)(asrc + 4 * s0);
        float4 as1 = *(const float4*)(asrc + 4 * s1);
        uint4 v0 = hh[(size_t)s0 * 32 + lane];   // 16B/lane -> 512B/warp gather
        uint4 v1 = hh[(size_t)s1 * 32 + lane];
        float e0 = ((head == 0) ? as0.x : (head == 1) ? as0.y : (head == 2) ? as0.z : as0.w) + adh;
        float e1 = ((head == 0) ? as1.x : (head == 1) ? as1.y : (head == 2) ? as1.z : as1.w) + adh;
        e0 = (e0 > 0.f) ? e0 : NEG_SLOPE * e0;
        e1 = (e1 > 0.f) ? e1 : NEG_SLOPE * e1;
        float w0 = expf(e0 - mh);
        float w1 = expf(e1 - mh);
        den0 += w0; den1 += w1;
        fma_half8(a0, v0, w0);
        fma_half8(a1, v1, w1);
    }
    if (j < end) {
        int s0 = g_col[j];
        float4 as0 = *(const float4*)(asrc + 4 * s0);
        uint4 v0 = hh[(size_t)s0 * 32 + lane];
        float e0 = ((head == 0) ? as0.x : (head == 1) ? as0.y : (head == 2) ? as0.z : as0.w) + adh;
        e0 = (e0 > 0.f) ? e0 : NEG_SLOPE * e0;
        float w0 = expf(e0 - mh);
        den0 += w0;
        fma_half8(a0, v0, w0);
    }

    float inv = 1.f / (den0 + den1 + 1e-16f);
    float r[8];
    #pragma unroll
    for (int k = 0; k < 8; k++) r[k] = (a0[k] + a1[k]) * inv;
    // mean over heads: butterfly over lane bits 3,4
    #pragma unroll
    for (int k = 0; k < 8; ++k) {
        r[k] += __shfl_xor_sync(0xFFFFFFFFu, r[k], 8);
        r[k] += __shfl_xor_sync(0xFFFFFFFFu, r[k], 16);
    }
    if (lane < 8) {
        float o_[8];
        #pragma unroll
        for (int k = 0; k < 8; ++k) {
            float v = 0.25f * r[k] + bias[lane * 8 + k];
            o_[k] = 1.f / (1.f + expf(-v));
        }
        float4* op = (float4*)(out + (size_t)warp * 64 + lane * 8);
        op[0] = make_float4(o_[0], o_[1], o_[2], o_[3]);
        op[1] = make_float4(o_[4], o_[5], o_[6], o_[7]);
    }
}

// ---------------- gate scalar: g[v] = relu(bn(out2@gw1+gb1)) @ gw2 + gb2 ----------------
__global__ void __launch_bounds__(64) gate_kernel(const float* __restrict__ x,
                                                  const float* __restrict__ gw1,
                                                  const float* __restrict__ gb1,
                                                  const float* __restrict__ gamma,
                                                  const float* __restrict__ beta,
                                                  const float* __restrict__ gw2,
                                                  const float* __restrict__ gb2,
                                                  float* __restrict__ gout, int N) {
    __shared__ float sW[64 * 64];
    __shared__ float sX[64 * 65];
    int tid = threadIdx.x;
    int vbase = blockIdx.x * 64;
    for (int i = tid; i < 4096; i += 64) sW[i] = gw1[i];
    for (int i = tid; i < 4096; i += 64) {
        int r = i >> 6, c = i & 63;
        int v = vbase + r;
        sX[r * 65 + c] = (v < N) ? x[(size_t)v * 64 + c] : 0.f;
    }
    __syncthreads();
    int v = vbase + tid;
    if (v >= N) return;
    float acc[64];
    #pragma unroll
    for (int j = 0; j < 64; ++j) acc[j] = 0.f;
    for (int c = 0; c < 64; ++c) {
        float xv = sX[tid * 65 + c];
        #pragma unroll
        for (int j = 0; j < 64; ++j) acc[j] += xv * sW[c * 64 + j];
    }
    float kinv = rsqrtf(1.0f + 1e-5f);
    float s = 0.f;
    #pragma unroll
    for (int j = 0; j < 64; ++j) {
        float t = (acc[j] + gb1[j]) * kinv * gamma[j] + beta[j];
        t = fmaxf(t, 0.f);
        s += t * gw2[j];
    }
    gout[v] = s + gb2[0];
}

// ---------------- per-graph boundaries (batch is sorted) ----------------
__global__ void gptr_kernel(int N) {
    int v = blockIdx.x * blockDim.x + threadIdx.x;
    if (v >= N) return;
    int b = g_batch[v];
    if (v == 0) {
        for (int i = 0; i <= b; i++) g_gptr[i] = 0;
    } else {
        int bp = g_batch[v - 1];
        for (int i = bp + 1; i <= b; i++) g_gptr[i] = v;
    }
    if (v == N - 1) {
        for (int i = b + 1; i <= GNUM; i++) g_gptr[i] = N;
    }
}

// ---------------- pooling: one block per graph, atomic-free ----------------
__global__ void __launch_bounds__(256) pool_kernel(const float* __restrict__ out2, int N) {
    int b = blockIdx.x;
    int start = g_gptr[b], end = g_gptr[b + 1];
    __shared__ float smax[256];
    __shared__ float sacc[256];
    __shared__ float sden[4];
    int tid = threadIdx.x;
    float m = -1e30f;
    for (int v = start + tid; v < end; v += 256) m = fmaxf(m, g_gate[v]);
    smax[tid] = m;
    __syncthreads();
    for (int s = 128; s; s >>= 1) {
        if (tid < s) smax[tid] = fmaxf(smax[tid], smax[tid + s]);
        __syncthreads();
    }
    float mx = smax[0];
    __syncthreads();
    int c = tid & 63;
    int sub = tid >> 6;
    float acc = 0.f, dacc = 0.f;
    for (int v = start + sub; v < end; v += 4) {
        float w = expf(g_gate[v] - mx);
        acc += w * out2[(size_t)v * 64 + c];
        if (c == 0) dacc += w;
    }
    sacc[tid] = acc;
    if (c == 0) sden[sub] = dacc;
    __syncthreads();
    if (sub == 0) g_pooled[b * 64 + c] = sacc[c] + sacc[64 + c] + sacc[128 + c] + sacc[192 + c];
    if (tid == 0) g_den[b] = sden[0] + sden[1] + sden[2] + sden[3];
}

__global__ void final_kernel(const float* __restrict__ lw, const float* __restrict__ lb,
                             float* __restrict__ out) {
    int g = threadIdx.x;
    if (g >= GNUM) return;
    float s = 0.f;
    for (int c = 0; c < 64; c++) s += g_pooled[g * 64 + c] * lw[c];
    s = s / (g_den[g] + 1e-16f) + lb[0];
    out[g] = 1.f / (1.f + expf(-s));
}

// ---------------- launch ----------------
extern "C" void kernel_launch(void* const* d_in, const int* in_sizes, int n_in,
                              void* d_out, int out_size) {
    const float* x  = (const float*)d_in[0];
    const void*  ei = d_in[1];
    const void*  bt = d_in[2];
    int o = (in_sizes[3] == 1) ? 1 : 0;   // optional num_graphs scalar input
    const float* W1  = (const float*)d_in[3 + o];
    const float* as1 = (const float*)d_in[4 + o];
    const float* ad1 = (const float*)d_in[5 + o];
    const float* b1  = (const float*)d_in[6 + o];
    const float* W2  = (const float*)d_in[7 + o];
    const float* as2 = (const float*)d_in[8 + o];
    const float* ad2 = (const float*)d_in[9 + o];
    const float* b2  = (const float*)d_in[10 + o];
    const float* gw1 = (const float*)d_in[11 + o];
    const float* gb1 = (const float*)d_in[12 + o];
    const float* gam = (const float*)d_in[13 + o];
    const float* bet = (const float*)d_in[14 + o];
    const float* gw2 = (const float*)d_in[15 + o];
    const float* gb2 = (const float*)d_in[16 + o];
    const float* lw  = (const float*)d_in[17 + o];
    const float* lb  = (const float*)d_in[18 + o];

    int N = in_sizes[0] / 128;
    int E = in_sizes[1] / 2;

    uint4* hhbuf; float *asrcb, *adstb, *out1b, *out2b, *gateb;
    cudaGetSymbolAddress((void**)&hhbuf, g_hh);
    cudaGetSymbolAddress((void**)&asrcb, g_asrc);
    cudaGetSymbolAddress((void**)&adstb, g_adst);
    cudaGetSymbolAddress((void**)&out1b, g_out1);
    cudaGetSymbolAddress((void**)&out2b, g_out2);
    cudaGetSymbolAddress((void**)&gateb, g_gate);

    // index normalization + CSR build
    detect_kernel<<<1, 32>>>((const long long*)ei);
    int convT = 2 * E + N;
    convert_kernel<<<(convT + 255) / 256, 256>>>(ei, bt, E, N);
    degree_kernel<<<(E + 255) / 256, 256>>>(E);
    scan_kernel<<<1, 1024>>>(N);
    scatter_kernel<<<(E + N + 255) / 256, 256>>>(E, N);

    dim3 ggrid(2, (N + 127) / 128);
    int wblocks = (N + 7) / 8;

    // layer 1
    sgemm_half_kernel<<<ggrid, 256>>>(x, W1, (__half*)hhbuf, N, 128);
    attn_kernel<<<wblocks, 256>>>((const __half*)hhbuf, as1, ad1, asrcb, adstb, N);
    aggregate_kernel<<<wblocks, 256>>>(hhbuf, asrcb, adstb, b1, out1b, N);

    // layer 2
    sgemm_half_kernel<<<ggrid, 256>>>(out1b, W2, (__half*)hhbuf, N, 64);
    attn_kernel<<<wblocks, 256>>>((const __half*)hhbuf, as2, ad2, asrcb, adstb, N);
    aggregate_kernel<<<wblocks, 256>>>(hhbuf, asrcb, adstb, b2, out2b, N);

    // pooling
    gate_kernel<<<(N + 63) / 64, 64>>>(out2b, gw1, gb1, gam, bet, gw2, gb2, gateb, N);
    gptr_kernel<<<(N + 255) / 256, 256>>>(N);
    pool_kernel<<<GNUM, 256>>>(out2b, N);
    final_kernel<<<1, 64>>>(lw, lb, (float*)d_out);
}

// round 4
// speedup vs baseline: 1.1411x; 1.0189x over previous
#include <cuda_runtime.h>
#include <cuda_fp16.h>
#include <math.h>
#include <stdint.h>

#define NNODES 50000
#define NEDGES 800000
#define TOTE   (NEDGES + NNODES)
#define GNUM   64
#define NEG_SLOPE 0.2f
#define SCAN_BS 256

// ---------------- static device scratch (no runtime allocation) ----------------
static __device__ int   g_is64;
static __device__ int   g_src[NEDGES];
static __device__ int   g_dst[NEDGES];
static __device__ int   g_batch[NNODES];
static __device__ int   g_deg[NNODES];
static __device__ int   g_row[NNODES + 1];
static __device__ int   g_cur[NNODES];
static __device__ int   g_col[TOTE];
static __device__ int   g_bsum[(NNODES + SCAN_BS - 1) / SCAN_BS + 1];
static __device__ int   g_boff[(NNODES + SCAN_BS - 1) / SCAN_BS + 1];
static __device__ int   g_gptr[GNUM + 1];
static __device__ uint4 g_hh[(size_t)NNODES * 32];   // h as fp16: 256 half = 32 uint4 per node
static __device__ float g_asrc[NNODES * 4];
static __device__ float g_adst[NNODES * 4];
static __device__ float g_out1[(size_t)NNODES * 64];
static __device__ float g_out2[(size_t)NNODES * 64];
static __device__ float g_gate[NNODES];
static __device__ float g_pooled[GNUM * 64];
static __device__ float g_den[GNUM];

// ---------------- prep: zero degree + detect index dtype ----------------
__global__ void prep_kernel(const long long* __restrict__ ei, int N) {
    int i = blockIdx.x * blockDim.x + threadIdx.x;
    if (i < N) g_deg[i] = 0;
    if (blockIdx.x == 0 && threadIdx.x < 32) {
        long long v = ei[threadIdx.x];
        int ok = (v >= 0 && v < (long long)N);
        unsigned all = __all_sync(0xFFFFFFFFu, ok);
        if (threadIdx.x == 0) g_is64 = all ? 1 : 0;
    }
}

// ---------------- convert indices + fused degree count ----------------
__global__ void convert_kernel(const void* __restrict__ ei, const void* __restrict__ bt,
                               int E, int N) {
    int i = blockIdx.x * blockDim.x + threadIdx.x;
    int total = 2 * E + N;
    if (i >= total) return;
    int is64 = g_is64;
    if (i < 2 * E) {
        int v = is64 ? (int)((const long long*)ei)[i] : ((const int*)ei)[i];
        if (i < E) g_src[i] = v;
        else { g_dst[i - E] = v; atomicAdd(&g_deg[v], 1); }
    } else {
        int j = i - 2 * E;
        int v = is64 ? (int)((const long long*)bt)[j] : ((const int*)bt)[j];
        g_batch[j] = v;
    }
}

// ---------------- 3-phase multi-block exclusive scan of (deg+1) ----------------
__global__ void scan1_kernel(int N) {
    __shared__ int ws[SCAN_BS / 32];
    int t = threadIdx.x, lane = t & 31, wid = t >> 5;
    int i = blockIdx.x * SCAN_BS + t;
    int x = (i < N) ? g_deg[i] + 1 : 0;   // +1 = self-loop
    int v = x;
    #pragma unroll
    for (int o = 1; o < 32; o <<= 1) {
        int u = __shfl_up_sync(0xFFFFFFFFu, v, o);
        if (lane >= o) v += u;
    }
    if (lane == 31) ws[wid] = v;
    __syncthreads();
    if (wid == 0) {
        // ALL 32 lanes participate in sync-shfls; inactive lanes carry 0
        int w = (lane < SCAN_BS / 32) ? ws[lane] : 0;
        #pragma unroll
        for (int o = 1; o < SCAN_BS / 32; o <<= 1) {
            int u = __shfl_up_sync(0xFFFFFFFFu, w, o);
            if (lane >= o) w += u;
        }
        if (lane < SCAN_BS / 32) ws[lane] = w;
    }
    __syncthreads();
    int incl = v + (wid ? ws[wid - 1] : 0);
    if (i < N) g_row[i] = incl - x;               // block-local exclusive
    if (t == SCAN_BS - 1) g_bsum[blockIdx.x] = incl;
}

__global__ void __launch_bounds__(1024) scan2_kernel(int nb) {
    __shared__ int ws[32];
    int t = threadIdx.x, lane = t & 31, wid = t >> 5;
    int x = (t < nb) ? g_bsum[t] : 0;
    int v = x;
    #pragma unroll
    for (int o = 1; o < 32; o <<= 1) {
        int u = __shfl_up_sync(0xFFFFFFFFu, v, o);
        if (lane >= o) v += u;
    }
    if (lane == 31) ws[wid] = v;
    __syncthreads();
    if (wid == 0) {
        int w = ws[lane];
        #pragma unroll
        for (int o = 1; o < 32; o <<= 1) {
            int u = __shfl_up_sync(0xFFFFFFFFu, w, o);
            if (lane >= o) w += u;
        }
        ws[lane] = w;
    }
    __syncthreads();
    int incl = v + (wid ? ws[wid - 1] : 0);
    if (t < nb) g_boff[t] = incl - x;
}

__global__ void scan3_kernel(int N, int E) {
    int i = blockIdx.x * blockDim.x + threadIdx.x;
    if (i < N) {
        int r = g_row[i] + g_boff[i >> 8];   // SCAN_BS = 256
        g_row[i] = r;
        g_cur[i] = r;
    }
    if (i == 0) g_row[N] = E + N;
}

__global__ void scatter_kernel(int E, int N) {
    int i = blockIdx.x * blockDim.x + threadIdx.x;
    if (i >= E + N) return;
    int s, d;
    if (i < E) { s = g_src[i]; d = g_dst[i]; }
    else       { s = d = i - E; }
    int pos = atomicAdd(&g_cur[d], 1);
    g_col[pos] = s;
}

// ---------------- SGEMM + fused attention-score epilogue ----------------
// C_half[M,256] = A[M,K] @ B[K,256]; also asrc/adst[M,4] from fp32 accumulators.
__global__ void __launch_bounds__(256) sgemm_half_kernel(const float* __restrict__ A,
                                                         const float* __restrict__ B,
                                                         __half* __restrict__ C,
                                                         const float* __restrict__ att_src,
                                                         const float* __restrict__ att_dst,
                                                         float* __restrict__ asrc,
                                                         float* __restrict__ adst,
                                                         int M, int K) {
    const int N = 256;
    __shared__ float As[8][128];
    __shared__ float Bs[8][128];
    int tid = threadIdx.x;
    int bx = blockIdx.x;   // N tiles (2): heads {2bx, 2bx+1}
    int by = blockIdx.y;   // M tiles
    int tx = tid & 15, ty = tid >> 4;
    int aRow = tid >> 1;
    int aCol = (tid & 1) * 4;
    int bRow = tid >> 5;
    int bCol = (tid & 31) * 4;
    float acc[8][8];
    #pragma unroll
    for (int i = 0; i < 8; i++)
        #pragma unroll
        for (int j = 0; j < 8; j++) acc[i][j] = 0.f;

    const float* Aptr = A + (size_t)(by * 128) * K;
    const float* Bptr = B + bx * 128;
    int gRow = by * 128 + aRow;

    for (int k0 = 0; k0 < K; k0 += 8) {
        float4 av = make_float4(0.f, 0.f, 0.f, 0.f);
        if (gRow < M) av = *(const float4*)(Aptr + (size_t)aRow * K + k0 + aCol);
        As[aCol + 0][aRow] = av.x;
        As[aCol + 1][aRow] = av.y;
        As[aCol + 2][aRow] = av.z;
        As[aCol + 3][aRow] = av.w;
        float4 bv = *(const float4*)(Bptr + (size_t)(k0 + bRow) * N + bCol);
        *(float4*)&Bs[bRow][bCol] = bv;
        __syncthreads();
        #pragma unroll
        for (int k = 0; k < 8; k++) {
            float ra[8], rb[8];
            #pragma unroll
            for (int i = 0; i < 8; i++) ra[i] = As[k][ty * 8 + i];
            #pragma unroll
            for (int j = 0; j < 8; j++) rb[j] = Bs[k][tx * 8 + j];
            #pragma unroll
            for (int i = 0; i < 8; i++)
                #pragma unroll
                for (int j = 0; j < 8; j++) acc[i][j] += ra[i] * rb[j];
        }
        __syncthreads();
    }
    // store fp16 h
    #pragma unroll
    for (int i = 0; i < 8; i++) {
        int row = by * 128 + ty * 8 + i;
        if (row >= M) continue;
        __half h8[8];
        #pragma unroll
        for (int j = 0; j < 8; j++) h8[j] = __float2half(acc[i][j]);
        *(uint4*)(C + (size_t)row * N + bx * 128 + tx * 8) = *(uint4*)h8;
    }
    // fused attention scores: head = bx*2 + (tx>>3); channels (tx&7)*8..+8
    int head = bx * 2 + (tx >> 3);
    int cbase = (tx & 7) * 8;
    float wsrc[8], wdst[8];
    #pragma unroll
    for (int j = 0; j < 8; j++) {
        wsrc[j] = __ldg(att_src + head * 64 + cbase + j);
        wdst[j] = __ldg(att_dst + head * 64 + cbase + j);
    }
    float ps[8], pd[8];
    #pragma unroll
    for (int i = 0; i < 8; i++) {
        float s = 0.f, d = 0.f;
        #pragma unroll
        for (int j = 0; j < 8; j++) { s += acc[i][j] * wsrc[j]; d += acc[i][j] * wdst[j]; }
        ps[i] = s; pd[i] = d;
    }
    #pragma unroll
    for (int o = 1; o < 8; o <<= 1) {
        #pragma unroll
        for (int i = 0; i < 8; i++) {
            ps[i] += __shfl_xor_sync(0xFFFFFFFFu, ps[i], o);
            pd[i] += __shfl_xor_sync(0xFFFFFFFFu, pd[i], o);
        }
    }
    if ((tx & 7) == 0) {
        #pragma unroll
        for (int i = 0; i < 8; i++) {
            int row = by * 128 + ty * 8 + i;
            if (row < M) { asrc[row * 4 + head] = ps[i]; adst[row * 4 + head] = pd[i]; }
        }
    }
}

// ---------------- GAT aggregation: warp per destination node, fp16 gather, 4x unrolled ----------------
__device__ __forceinline__ void fma_half8(float* a, uint4 v, float w) {
    __half2* p = (__half2*)&v;
    #pragma unroll
    for (int q = 0; q < 4; q++) {
        float2 f = __half22float2(p[q]);
        a[2 * q]     += w * f.x;
        a[2 * q + 1] += w * f.y;
    }
}

__device__ __forceinline__ float pick(float4 v, int head, float adh) {
    float e = ((head == 0) ? v.x : (head == 1) ? v.y : (head == 2) ? v.z : v.w) + adh;
    return (e > 0.f) ? e : NEG_SLOPE * e;
}

__global__ void __launch_bounds__(256) aggregate_kernel(const uint4* __restrict__ hh,
                                                        const float* __restrict__ asrc,
                                                        const float* __restrict__ adst,
                                                        const float* __restrict__ bias,
                                                        float* __restrict__ out, int N) {
    int warp = (blockIdx.x * blockDim.x + threadIdx.x) >> 5;
    if (warp >= N) return;
    int lane = threadIdx.x & 31;
    int start = g_row[warp], end = g_row[warp + 1];
    float4 ad = *(const float4*)(adst + 4 * warp);

    // pass 1: per-head max over incoming edges
    float m0 = -1e30f, m1 = -1e30f, m2 = -1e30f, m3 = -1e30f;
    for (int j = start + lane; j < end; j += 32) {
        int s = g_col[j];
        float4 as = *(const float4*)(asrc + 4 * s);
        float e0 = as.x + ad.x; e0 = (e0 > 0.f) ? e0 : NEG_SLOPE * e0;
        float e1 = as.y + ad.y; e1 = (e1 > 0.f) ? e1 : NEG_SLOPE * e1;
        float e2 = as.z + ad.z; e2 = (e2 > 0.f) ? e2 : NEG_SLOPE * e2;
        float e3 = as.w + ad.w; e3 = (e3 > 0.f) ? e3 : NEG_SLOPE * e3;
        m0 = fmaxf(m0, e0); m1 = fmaxf(m1, e1); m2 = fmaxf(m2, e2); m3 = fmaxf(m3, e3);
    }
    #pragma unroll
    for (int o = 16; o; o >>= 1) {
        m0 = fmaxf(m0, __shfl_xor_sync(0xFFFFFFFFu, m0, o));
        m1 = fmaxf(m1, __shfl_xor_sync(0xFFFFFFFFu, m1, o));
        m2 = fmaxf(m2, __shfl_xor_sync(0xFFFFFFFFu, m2, o));
        m3 = fmaxf(m3, __shfl_xor_sync(0xFFFFFFFFu, m3, o));
    }
    int head = lane >> 3;
    float mh  = (head == 0) ? m0 : (head == 1) ? m1 : (head == 2) ? m2 : m3;
    float adh = (head == 0) ? ad.x : (head == 1) ? ad.y : (head == 2) ? ad.z : ad.w;

    // pass 2: 4 independent edge chains in flight
    float a0[8], a1[8], a2[8], a3[8];
    #pragma unroll
    for (int k = 0; k < 8; k++) { a0[k] = 0.f; a1[k] = 0.f; a2[k] = 0.f; a3[k] = 0.f; }
    float den = 0.f;

    int j = start;
    for (; j + 4 <= end; j += 4) {
        int s0 = g_col[j], s1 = g_col[j + 1], s2 = g_col[j + 2], s3 = g_col[j + 3];
        float4 q0 = *(const float4*)(asrc + 4 * s0);
        float4 q1 = *(const float4*)(asrc + 4 * s1);
        float4 q2 = *(const float4*)(asrc + 4 * s2);
        float4 q3 = *(const float4*)(asrc + 4 * s3);
        uint4 v0 = hh[(size_t)s0 * 32 + lane];
        uint4 v1 = hh[(size_t)s1 * 32 + lane];
        uint4 v2 = hh[(size_t)s2 * 32 + lane];
        uint4 v3 = hh[(size_t)s3 * 32 + lane];
        float w0 = expf(pick(q0, head, adh) - mh);
        float w1 = expf(pick(q1, head, adh) - mh);
        float w2 = expf(pick(q2, head, adh) - mh);
        float w3 = expf(pick(q3, head, adh) - mh);
        den += (w0 + w1) + (w2 + w3);
        fma_half8(a0, v0, w0);
        fma_half8(a1, v1, w1);
        fma_half8(a2, v2, w2);
        fma_half8(a3, v3, w3);
    }
    for (; j < end; ++j) {
        int s0 = g_col[j];
        float4 q0 = *(const float4*)(asrc + 4 * s0);
        uint4 v0 = hh[(size_t)s0 * 32 + lane];
        float w0 = expf(pick(q0, head, adh) - mh);
        den += w0;
        fma_half8(a0, v0, w0);
    }

    float inv = 1.f / (den + 1e-16f);
    float r[8];
    #pragma unroll
    for (int k = 0; k < 8; k++) r[k] = ((a0[k] + a1[k]) + (a2[k] + a3[k])) * inv;
    #pragma unroll
    for (int k = 0; k < 8; ++k) {
        r[k] += __shfl_xor_sync(0xFFFFFFFFu, r[k], 8);
        r[k] += __shfl_xor_sync(0xFFFFFFFFu, r[k], 16);
    }
    if (lane < 8) {
        float o_[8];
        #pragma unroll
        for (int k = 0; k < 8; ++k) {
            float v = 0.25f * r[k] + bias[lane * 8 + k];
            o_[k] = 1.f / (1.f + expf(-v));
        }
        float4* op = (float4*)(out + (size_t)warp * 64 + lane * 8);
        op[0] = make_float4(o_[0], o_[1], o_[2], o_[3]);
        op[1] = make_float4(o_[4], o_[5], o_[6], o_[7]);
    }
}

// ---------------- gate scalar ----------------
__global__ void __launch_bounds__(64) gate_kernel(const float* __restrict__ x,
                                                  const float* __restrict__ gw1,
                                                  const float* __restrict__ gb1,
                                                  const float* __restrict__ gamma,
                                                  const float* __restrict__ beta,
                                                  const float* __restrict__ gw2,
                                                  const float* __restrict__ gb2,
                                                  float* __restrict__ gout, int N) {
    __shared__ float sW[64 * 64];
    __shared__ float sX[64 * 65];
    int tid = threadIdx.x;
    int vbase = blockIdx.x * 64;
    for (int i = tid; i < 4096; i += 64) sW[i] = gw1[i];
    for (int i = tid; i < 4096; i += 64) {
        int r = i >> 6, c = i & 63;
        int v = vbase + r;
        sX[r * 65 + c] = (v < N) ? x[(size_t)v * 64 + c] : 0.f;
    }
    __syncthreads();
    int v = vbase + tid;
    if (v >= N) return;
    float acc[64];
    #pragma unroll
    for (int j = 0; j < 64; ++j) acc[j] = 0.f;
    for (int c = 0; c < 64; ++c) {
        float xv = sX[tid * 65 + c];
        #pragma unroll
        for (int j = 0; j < 64; ++j) acc[j] += xv * sW[c * 64 + j];
    }
    float kinv = rsqrtf(1.0f + 1e-5f);
    float s = 0.f;
    #pragma unroll
    for (int j = 0; j < 64; ++j) {
        float t = (acc[j] + gb1[j]) * kinv * gamma[j] + beta[j];
        t = fmaxf(t, 0.f);
        s += t * gw2[j];
    }
    gout[v] = s + gb2[0];
}

// ---------------- per-graph boundaries (batch sorted) ----------------
__global__ void gptr_kernel(int N) {
    int v = blockIdx.x * blockDim.x + threadIdx.x;
    if (v >= N) return;
    int b = g_batch[v];
    if (v == 0) {
        for (int i = 0; i <= b; i++) g_gptr[i] = 0;
    } else {
        int bp = g_batch[v - 1];
        for (int i = bp + 1; i <= b; i++) g_gptr[i] = v;
    }
    if (v == N - 1) {
        for (int i = b + 1; i <= GNUM; i++) g_gptr[i] = N;
    }
}

// ---------------- pooling ----------------
__global__ void __launch_bounds__(256) pool_kernel(const float* __restrict__ out2, int N) {
    int b = blockIdx.x;
    int start = g_gptr[b], end = g_gptr[b + 1];
    __shared__ float smax[256];
    __shared__ float sacc[256];
    __shared__ float sden[4];
    int tid = threadIdx.x;
    float m = -1e30f;
    for (int v = start + tid; v < end; v += 256) m = fmaxf(m, g_gate[v]);
    smax[tid] = m;
    __syncthreads();
    for (int s = 128; s; s >>= 1) {
        if (tid < s) smax[tid] = fmaxf(smax[tid], smax[tid + s]);
        __syncthreads();
    }
    float mx = smax[0];
    __syncthreads();
    int c = tid & 63;
    int sub = tid >> 6;
    float acc = 0.f, dacc = 0.f;
    for (int v = start + sub; v < end; v += 4) {
        float w = expf(g_gate[v] - mx);
        acc += w * out2[(size_t)v * 64 + c];
        if (c == 0) dacc += w;
    }
    sacc[tid] = acc;
    if (c == 0) sden[sub] = dacc;
    __syncthreads();
    if (sub == 0) g_pooled[b * 64 + c] = sacc[c] + sacc[64 + c] + sacc[128 + c] + sacc[192 + c];
    if (tid == 0) g_den[b] = sden[0] + sden[1] + sden[2] + sden[3];
}

__global__ void final_kernel(const float* __restrict__ lw, const float* __restrict__ lb,
                             float* __restrict__ out) {
    int g = threadIdx.x;
    if (g >= GNUM) return;
    float s = 0.f;
    for (int c = 0; c < 64; c++) s += g_pooled[g * 64 + c] * lw[c];
    s = s / (g_den[g] + 1e-16f) + lb[0];
    out[g] = 1.f / (1.f + expf(-s));
}

// ---------------- launch ----------------
extern "C" void kernel_launch(void* const* d_in, const int* in_sizes, int n_in,
                              void* d_out, int out_size) {
    const float* x  = (const float*)d_in[0];
    const void*  ei = d_in[1];
    const void*  bt = d_in[2];
    int o = (in_sizes[3] == 1) ? 1 : 0;   // optional num_graphs scalar input
    const float* W1  = (const float*)d_in[3 + o];
    const float* as1 = (const float*)d_in[4 + o];
    const float* ad1 = (const float*)d_in[5 + o];
    const float* b1  = (const float*)d_in[6 + o];
    const float* W2  = (const float*)d_in[7 + o];
    const float* as2 = (const float*)d_in[8 + o];
    const float* ad2 = (const float*)d_in[9 + o];
    const float* b2  = (const float*)d_in[10 + o];
    const float* gw1 = (const float*)d_in[11 + o];
    const float* gb1 = (const float*)d_in[12 + o];
    const float* gam = (const float*)d_in[13 + o];
    const float* bet = (const float*)d_in[14 + o];
    const float* gw2 = (const float*)d_in[15 + o];
    const float* gb2 = (const float*)d_in[16 + o];
    const float* lw  = (const float*)d_in[17 + o];
    const float* lb  = (const float*)d_in[18 + o];

    int N = in_sizes[0] / 128;
    int E = in_sizes[1] / 2;

    uint4* hhbuf; float *asrcb, *adstb, *out1b, *out2b, *gateb;
    cudaGetSymbolAddress((void**)&hhbuf, g_hh);
    cudaGetSymbolAddress((void**)&asrcb, g_asrc);
    cudaGetSymbolAddress((void**)&adstb, g_adst);
    cudaGetSymbolAddress((void**)&out1b, g_out1);
    cudaGetSymbolAddress((void**)&out2b, g_out2);
    cudaGetSymbolAddress((void**)&gateb, g_gate);

    int nb = (N + SCAN_BS - 1) / SCAN_BS;

    // CSR build
    prep_kernel<<<(N + 255) / 256, 256>>>((const long long*)ei, N);
    int convT = 2 * E + N;
    convert_kernel<<<(convT + 255) / 256, 256>>>(ei, bt, E, N);
    scan1_kernel<<<nb, SCAN_BS>>>(N);
    scan2_kernel<<<1, 1024>>>(nb);
    scan3_kernel<<<(N + 255) / 256, 256>>>(N, E);
    scatter_kernel<<<(E + N + 255) / 256, 256>>>(E, N);

    dim3 ggrid(2, (N + 127) / 128);
    int wblocks = (N + 7) / 8;

    // layer 1 (GEMM + fused attention scores)
    sgemm_half_kernel<<<ggrid, 256>>>(x, W1, (__half*)hhbuf, as1, ad1, asrcb, adstb, N, 128);
    aggregate_kernel<<<wblocks, 256>>>(hhbuf, asrcb, adstb, b1, out1b, N);

    // layer 2
    sgemm_half_kernel<<<ggrid, 256>>>(out1b, W2, (__half*)hhbuf, as2, ad2, asrcb, adstb, N, 64);
    aggregate_kernel<<<wblocks, 256>>>(hhbuf, asrcb, adstb, b2, out2b, N);

    // pooling
    gate_kernel<<<(N + 63) / 64, 64>>>(out2b, gw1, gb1, gam, bet, gw2, gb2, gateb, N);
    gptr_kernel<<<(N + 255) / 256, 256>>>(N);
    pool_kernel<<<GNUM, 256>>>(out2b, N);
    final_kernel<<<1, 64>>>(lw, lb, (float*)d_out);
}

// round 5
// speedup vs baseline: 1.3082x; 1.1464x over previous
#include <cuda_runtime.h>
#include <cuda_fp16.h>
#include <mma.h>
#include <math.h>
#include <stdint.h>

using namespace nvcuda;

#define NNODES 50000
#define NPAD   50048            // padded to 64-row multiple for wmma tiles
#define NEDGES 800000
#define TOTE   (NEDGES + NNODES)
#define GNUM   64
#define NEG_SLOPE 0.2f
#define SCAN_BS 256

// ---------------- static device scratch (no runtime allocation) ----------------
static __device__ int    g_is64;
static __device__ int    g_src[NEDGES];
static __device__ int    g_dst[NEDGES];
static __device__ int    g_batch[NNODES];
static __device__ int    g_deg[NNODES];
static __device__ int    g_row[NNODES + 1];
static __device__ int    g_cur[NNODES];
static __device__ int    g_col[TOTE];
static __device__ int    g_bsum[(NNODES + SCAN_BS - 1) / SCAN_BS + 1];
static __device__ int    g_boff[(NNODES + SCAN_BS - 1) / SCAN_BS + 1];
static __device__ int    g_gptr[GNUM + 1];
static __device__ __half g_x16[(size_t)NPAD * 128];   // fp16 copy of x (padding rows stay 0)
static __device__ __half g_w1h[128 * 256];
static __device__ __half g_w2h[64 * 256];
static __device__ __half g_o16[(size_t)NPAD * 64];    // fp16 copy of layer-1 output
static __device__ uint4  g_hh[(size_t)NPAD * 32];     // h fp16: 256 half = 32 uint4 per node
static __device__ float  g_asrc[NPAD * 4];
static __device__ float  g_adst[NPAD * 4];
static __device__ float  g_out1[(size_t)NNODES * 64];
static __device__ float  g_out2[(size_t)NNODES * 64];
static __device__ float  g_gate[NNODES];
static __device__ float  g_pooled[GNUM * 64];
static __device__ float  g_den[GNUM];

// ---------------- prep: zero degree + detect dtype + convert W to fp16 ----------------
__global__ void prep_kernel(const long long* __restrict__ ei,
                            const float* __restrict__ W1,
                            const float* __restrict__ W2, int N) {
    int i = blockIdx.x * blockDim.x + threadIdx.x;
    if (i < N) g_deg[i] = 0;
    if (i < 128 * 256) g_w1h[i] = __float2half(W1[i]);
    if (i < 64 * 256)  g_w2h[i] = __float2half(W2[i]);
    if (blockIdx.x == 0 && threadIdx.x < 32) {
        long long v = ei[threadIdx.x];
        int ok = (v >= 0 && v < (long long)N);
        unsigned all = __all_sync(0xFFFFFFFFu, ok);
        if (threadIdx.x == 0) g_is64 = all ? 1 : 0;
    }
}

// ---------------- x -> fp16 (8 elements per thread) ----------------
__global__ void xcvt_kernel(const float* __restrict__ x, int total8) {
    int i = blockIdx.x * blockDim.x + threadIdx.x;
    if (i >= total8) return;
    float4 a = ((const float4*)x)[2 * i];
    float4 b = ((const float4*)x)[2 * i + 1];
    __half h8[8] = {__float2half(a.x), __float2half(a.y), __float2half(a.z), __float2half(a.w),
                    __float2half(b.x), __float2half(b.y), __float2half(b.z), __float2half(b.w)};
    ((uint4*)g_x16)[i] = *(uint4*)h8;
}

// ---------------- convert indices + fused degree count ----------------
__global__ void convert_kernel(const void* __restrict__ ei, const void* __restrict__ bt,
                               int E, int N) {
    int i = blockIdx.x * blockDim.x + threadIdx.x;
    int total = 2 * E + N;
    if (i >= total) return;
    int is64 = g_is64;
    if (i < 2 * E) {
        int v = is64 ? (int)((const long long*)ei)[i] : ((const int*)ei)[i];
        if (i < E) g_src[i] = v;
        else { g_dst[i - E] = v; atomicAdd(&g_deg[v], 1); }
    } else {
        int j = i - 2 * E;
        int v = is64 ? (int)((const long long*)bt)[j] : ((const int*)bt)[j];
        g_batch[j] = v;
    }
}

// ---------------- 3-phase multi-block exclusive scan of (deg+1) ----------------
__global__ void scan1_kernel(int N) {
    __shared__ int ws[SCAN_BS / 32];
    int t = threadIdx.x, lane = t & 31, wid = t >> 5;
    int i = blockIdx.x * SCAN_BS + t;
    int x = (i < N) ? g_deg[i] + 1 : 0;
    int v = x;
    #pragma unroll
    for (int o = 1; o < 32; o <<= 1) {
        int u = __shfl_up_sync(0xFFFFFFFFu, v, o);
        if (lane >= o) v += u;
    }
    if (lane == 31) ws[wid] = v;
    __syncthreads();
    if (wid == 0) {
        int w = (lane < SCAN_BS / 32) ? ws[lane] : 0;
        #pragma unroll
        for (int o = 1; o < SCAN_BS / 32; o <<= 1) {
            int u = __shfl_up_sync(0xFFFFFFFFu, w, o);
            if (lane >= o) w += u;
        }
        if (lane < SCAN_BS / 32) ws[lane] = w;
    }
    __syncthreads();
    int incl = v + (wid ? ws[wid - 1] : 0);
    if (i < N) g_row[i] = incl - x;
    if (t == SCAN_BS - 1) g_bsum[blockIdx.x] = incl;
}

__global__ void __launch_bounds__(1024) scan2_kernel(int nb) {
    __shared__ int ws[32];
    int t = threadIdx.x, lane = t & 31, wid = t >> 5;
    int x = (t < nb) ? g_bsum[t] : 0;
    int v = x;
    #pragma unroll
    for (int o = 1; o < 32; o <<= 1) {
        int u = __shfl_up_sync(0xFFFFFFFFu, v, o);
        if (lane >= o) v += u;
    }
    if (lane == 31) ws[wid] = v;
    __syncthreads();
    if (wid == 0) {
        int w = ws[lane];
        #pragma unroll
        for (int o = 1; o < 32; o <<= 1) {
            int u = __shfl_up_sync(0xFFFFFFFFu, w, o);
            if (lane >= o) w += u;
        }
        ws[lane] = w;
    }
    __syncthreads();
    int incl = v + (wid ? ws[wid - 1] : 0);
    if (t < nb) g_boff[t] = incl - x;
}

__global__ void scan3_kernel(int N, int E) {
    int i = blockIdx.x * blockDim.x + threadIdx.x;
    if (i < N) {
        int r = g_row[i] + g_boff[i >> 8];
        g_row[i] = r;
        g_cur[i] = r;
    }
    if (i == 0) g_row[N] = E + N;
}

__global__ void scatter_kernel(int E, int N) {
    int i = blockIdx.x * blockDim.x + threadIdx.x;
    if (i >= E + N) return;
    int s, d;
    if (i < E) { s = g_src[i]; d = g_dst[i]; }
    else       { s = d = i - E; }
    int pos = atomicAdd(&g_cur[d], 1);
    g_col[pos] = s;
}

// ---------------- tensor-core GEMM + fused attention-score epilogue ----------------
// h[M,256] = A16[M,K] @ B16[K,256] (fp16 in, fp32 accum), h stored fp16.
// Block = 64 rows x 64 cols; bx = head (0..3), by = row tile. 4 warps, 16 rows each.
__global__ void __launch_bounds__(128) gemm_attn_kernel(const __half* __restrict__ A,
                                                        const __half* __restrict__ B,
                                                        uint4* __restrict__ C,
                                                        const float* __restrict__ att_src,
                                                        const float* __restrict__ att_dst,
                                                        float* __restrict__ asrc,
                                                        float* __restrict__ adst,
                                                        int K) {
    __shared__ float Cs[64 * 68];
    int tid = threadIdx.x;
    int warp = tid >> 5;
    int bx = blockIdx.x;       // head
    int by = blockIdx.y;       // 64-row tile
    int row0 = by * 64 + warp * 16;

    wmma::fragment<wmma::accumulator, 16, 16, 16, float> cf[4];
    #pragma unroll
    for (int n = 0; n < 4; n++) wmma::fill_fragment(cf[n], 0.f);

    for (int k0 = 0; k0 < K; k0 += 16) {
        wmma::fragment<wmma::matrix_a, 16, 16, 16, __half, wmma::row_major> af;
        wmma::load_matrix_sync(af, A + (size_t)row0 * K + k0, K);
        #pragma unroll
        for (int n = 0; n < 4; n++) {
            wmma::fragment<wmma::matrix_b, 16, 16, 16, __half, wmma::row_major> bf;
            wmma::load_matrix_sync(bf, B + (size_t)k0 * 256 + bx * 64 + n * 16, 256);
            wmma::mma_sync(cf[n], af, bf, cf[n]);
        }
    }
    #pragma unroll
    for (int n = 0; n < 4; n++)
        wmma::store_matrix_sync(Cs + warp * 16 * 68 + n * 16, cf[n], 68, wmma::mem_row_major);
    __syncthreads();

    // epilogue: 2 threads per row; each handles 32 cols
    int r = tid >> 1;
    int ch = (tid & 1) * 32;
    int row = by * 64 + r;
    float s = 0.f, d = 0.f;
    __half h16[32];
    #pragma unroll
    for (int c = 0; c < 32; c++) {
        float v = Cs[r * 68 + ch + c];
        s += v * __ldg(att_src + bx * 64 + ch + c);
        d += v * __ldg(att_dst + bx * 64 + ch + c);
        h16[c] = __float2half(v);
    }
    // store 32 halves = 4 uint4
    uint4* dst = C + (size_t)row * 32 + bx * 8 + (ch >> 3);
    uint4* src = (uint4*)h16;
    #pragma unroll
    for (int q = 0; q < 4; q++) dst[q] = src[q];
    // combine the two 32-col partials (pair lanes differ in bit 0)
    s += __shfl_xor_sync(0xFFFFFFFFu, s, 1);
    d += __shfl_xor_sync(0xFFFFFFFFu, d, 1);
    if ((tid & 1) == 0) {
        asrc[row * 4 + bx] = s;
        adst[row * 4 + bx] = d;
    }
}

// ---------------- GAT aggregation: warp per destination node, fp16 gather, 2x unrolled ----------------
__device__ __forceinline__ void fma_half8(float* a, uint4 v, float w) {
    __half2* p = (__half2*)&v;
    #pragma unroll
    for (int q = 0; q < 4; q++) {
        float2 f = __half22float2(p[q]);
        a[2 * q]     += w * f.x;
        a[2 * q + 1] += w * f.y;
    }
}

__global__ void __launch_bounds__(256) aggregate_kernel(const uint4* __restrict__ hh,
                                                        const float* __restrict__ asrc,
                                                        const float* __restrict__ adst,
                                                        const float* __restrict__ bias,
                                                        float* __restrict__ out,
                                                        uint4* __restrict__ out16,
                                                        int N) {
    int warp = (blockIdx.x * blockDim.x + threadIdx.x) >> 5;
    if (warp >= N) return;
    int lane = threadIdx.x & 31;
    int start = g_row[warp], end = g_row[warp + 1];
    float4 ad = *(const float4*)(adst + 4 * warp);

    // pass 1: per-head max
    float m0 = -1e30f, m1 = -1e30f, m2 = -1e30f, m3 = -1e30f;
    for (int j = start + lane; j < end; j += 32) {
        int s = g_col[j];
        float4 as = *(const float4*)(asrc + 4 * s);
        float e0 = as.x + ad.x; e0 = (e0 > 0.f) ? e0 : NEG_SLOPE * e0;
        float e1 = as.y + ad.y; e1 = (e1 > 0.f) ? e1 : NEG_SLOPE * e1;
        float e2 = as.z + ad.z; e2 = (e2 > 0.f) ? e2 : NEG_SLOPE * e2;
        float e3 = as.w + ad.w; e3 = (e3 > 0.f) ? e3 : NEG_SLOPE * e3;
        m0 = fmaxf(m0, e0); m1 = fmaxf(m1, e1); m2 = fmaxf(m2, e2); m3 = fmaxf(m3, e3);
    }
    #pragma unroll
    for (int o = 16; o; o >>= 1) {
        m0 = fmaxf(m0, __shfl_xor_sync(0xFFFFFFFFu, m0, o));
        m1 = fmaxf(m1, __shfl_xor_sync(0xFFFFFFFFu, m1, o));
        m2 = fmaxf(m2, __shfl_xor_sync(0xFFFFFFFFu, m2, o));
        m3 = fmaxf(m3, __shfl_xor_sync(0xFFFFFFFFu, m3, o));
    }
    int head = lane >> 3;
    float mh  = (head == 0) ? m0 : (head == 1) ? m1 : (head == 2) ? m2 : m3;
    float adh = (head == 0) ? ad.x : (head == 1) ? ad.y : (head == 2) ? ad.z : ad.w;

    // pass 2: 2 edges in flight
    float a0[8], a1[8];
    #pragma unroll
    for (int k = 0; k < 8; k++) { a0[k] = 0.f; a1[k] = 0.f; }
    float den0 = 0.f, den1 = 0.f;

    int j = start;
    for (; j + 2 <= end; j += 2) {
        int s0 = g_col[j];
        int s1 = g_col[j + 1];
        float4 q0 = *(const float4*)(asrc + 4 * s0);
        float4 q1 = *(const float4*)(asrc + 4 * s1);
        uint4 v0 = hh[(size_t)s0 * 32 + lane];
        uint4 v1 = hh[(size_t)s1 * 32 + lane];
        float e0 = ((head == 0) ? q0.x : (head == 1) ? q0.y : (head == 2) ? q0.z : q0.w) + adh;
        float e1 = ((head == 0) ? q1.x : (head == 1) ? q1.y : (head == 2) ? q1.z : q1.w) + adh;
        e0 = (e0 > 0.f) ? e0 : NEG_SLOPE * e0;
        e1 = (e1 > 0.f) ? e1 : NEG_SLOPE * e1;
        float w0 = expf(e0 - mh);
        float w1 = expf(e1 - mh);
        den0 += w0; den1 += w1;
        fma_half8(a0, v0, w0);
        fma_half8(a1, v1, w1);
    }
    if (j < end) {
        int s0 = g_col[j];
        float4 q0 = *(const float4*)(asrc + 4 * s0);
        uint4 v0 = hh[(size_t)s0 * 32 + lane];
        float e0 = ((head == 0) ? q0.x : (head == 1) ? q0.y : (head == 2) ? q0.z : q0.w) + adh;
        e0 = (e0 > 0.f) ? e0 : NEG_SLOPE * e0;
        float w0 = expf(e0 - mh);
        den0 += w0;
        fma_half8(a0, v0, w0);
    }

    float inv = 1.f / (den0 + den1 + 1e-16f);
    float r[8];
    #pragma unroll
    for (int k = 0; k < 8; k++) r[k] = (a0[k] + a1[k]) * inv;
    #pragma unroll
    for (int k = 0; k < 8; ++k) {
        r[k] += __shfl_xor_sync(0xFFFFFFFFu, r[k], 8);
        r[k] += __shfl_xor_sync(0xFFFFFFFFu, r[k], 16);
    }
    if (lane < 8) {
        float o_[8];
        __half h8[8];
        #pragma unroll
        for (int k = 0; k < 8; ++k) {
            float v = 0.25f * r[k] + bias[lane * 8 + k];
            float sg = 1.f / (1.f + expf(-v));
            o_[k] = sg;
            h8[k] = __float2half(sg);
        }
        float4* op = (float4*)(out + (size_t)warp * 64 + lane * 8);
        op[0] = make_float4(o_[0], o_[1], o_[2], o_[3]);
        op[1] = make_float4(o_[4], o_[5], o_[6], o_[7]);
        out16[(size_t)warp * 8 + lane] = *(uint4*)h8;
    }
}

// ---------------- gate scalar ----------------
__global__ void __launch_bounds__(64) gate_kernel(const float* __restrict__ x,
                                                  const float* __restrict__ gw1,
                                                  const float* __restrict__ gb1,
                                                  const float* __restrict__ gamma,
                                                  const float* __restrict__ beta,
                                                  const float* __restrict__ gw2,
                                                  const float* __restrict__ gb2,
                                                  float* __restrict__ gout, int N) {
    __shared__ float sW[64 * 64];
    __shared__ float sX[64 * 65];
    int tid = threadIdx.x;
    int vbase = blockIdx.x * 64;
    for (int i = tid; i < 4096; i += 64) sW[i] = gw1[i];
    for (int i = tid; i < 4096; i += 64) {
        int r = i >> 6, c = i & 63;
        int v = vbase + r;
        sX[r * 65 + c] = (v < N) ? x[(size_t)v * 64 + c] : 0.f;
    }
    __syncthreads();
    int v = vbase + tid;
    if (v >= N) return;
    float acc[64];
    #pragma unroll
    for (int j = 0; j < 64; ++j) acc[j] = 0.f;
    for (int c = 0; c < 64; ++c) {
        float xv = sX[tid * 65 + c];
        #pragma unroll
        for (int j = 0; j < 64; ++j) acc[j] += xv * sW[c * 64 + j];
    }
    float kinv = rsqrtf(1.0f + 1e-5f);
    float s = 0.f;
    #pragma unroll
    for (int j = 0; j < 64; ++j) {
        float t = (acc[j] + gb1[j]) * kinv * gamma[j] + beta[j];
        t = fmaxf(t, 0.f);
        s += t * gw2[j];
    }
    gout[v] = s + gb2[0];
}

// ---------------- per-graph boundaries (batch sorted) ----------------
__global__ void gptr_kernel(int N) {
    int v = blockIdx.x * blockDim.x + threadIdx.x;
    if (v >= N) return;
    int b = g_batch[v];
    if (v == 0) {
        for (int i = 0; i <= b; i++) g_gptr[i] = 0;
    } else {
        int bp = g_batch[v - 1];
        for (int i = bp + 1; i <= b; i++) g_gptr[i] = v;
    }
    if (v == N - 1) {
        for (int i = b + 1; i <= GNUM; i++) g_gptr[i] = N;
    }
}

// ---------------- pooling ----------------
__global__ void __launch_bounds__(256) pool_kernel(const float* __restrict__ out2, int N) {
    int b = blockIdx.x;
    int start = g_gptr[b], end = g_gptr[b + 1];
    __shared__ float smax[256];
    __shared__ float sacc[256];
    __shared__ float sden[4];
    int tid = threadIdx.x;
    float m = -1e30f;
    for (int v = start + tid; v < end; v += 256) m = fmaxf(m, g_gate[v]);
    smax[tid] = m;
    __syncthreads();
    for (int s = 128; s; s >>= 1) {
        if (tid < s) smax[tid] = fmaxf(smax[tid], smax[tid + s]);
        __syncthreads();
    }
    float mx = smax[0];
    __syncthreads();
    int c = tid & 63;
    int sub = tid >> 6;
    float acc = 0.f, dacc = 0.f;
    for (int v = start + sub; v < end; v += 4) {
        float w = expf(g_gate[v] - mx);
        acc += w * out2[(size_t)v * 64 + c];
        if (c == 0) dacc += w;
    }
    sacc[tid] = acc;
    if (c == 0) sden[sub] = dacc;
    __syncthreads();
    if (sub == 0) g_pooled[b * 64 + c] = sacc[c] + sacc[64 + c] + sacc[128 + c] + sacc[192 + c];
    if (tid == 0) g_den[b] = sden[0] + sden[1] + sden[2] + sden[3];
}

__global__ void final_kernel(const float* __restrict__ lw, const float* __restrict__ lb,
                             float* __restrict__ out) {
    int g = threadIdx.x;
    if (g >= GNUM) return;
    float s = 0.f;
    for (int c = 0; c < 64; c++) s += g_pooled[g * 64 + c] * lw[c];
    s = s / (g_den[g] + 1e-16f) + lb[0];
    out[g] = 1.f / (1.f + expf(-s));
}

// ---------------- launch ----------------
extern "C" void kernel_launch(void* const* d_in, const int* in_sizes, int n_in,
                              void* d_out, int out_size) {
    const float* x  = (const float*)d_in[0];
    const void*  ei = d_in[1];
    const void*  bt = d_in[2];
    int o = (in_sizes[3] == 1) ? 1 : 0;   // optional num_graphs scalar input
    const float* W1  = (const float*)d_in[3 + o];
    const float* as1 = (const float*)d_in[4 + o];
    const float* ad1 = (const float*)d_in[5 + o];
    const float* b1  = (const float*)d_in[6 + o];
    const float* W2  = (const float*)d_in[7 + o];
    const float* as2 = (const float*)d_in[8 + o];
    const float* ad2 = (const float*)d_in[9 + o];
    const float* b2  = (const float*)d_in[10 + o];
    const float* gw1 = (const float*)d_in[11 + o];
    const float* gb1 = (const float*)d_in[12 + o];
    const float* gam = (const float*)d_in[13 + o];
    const float* bet = (const float*)d_in[14 + o];
    const float* gw2 = (const float*)d_in[15 + o];
    const float* gb2 = (const float*)d_in[16 + o];
    const float* lw  = (const float*)d_in[17 + o];
    const float* lb  = (const float*)d_in[18 + o];

    int N = in_sizes[0] / 128;
    int E = in_sizes[1] / 2;

    __half *x16b, *w1hb, *w2hb, *o16b;
    uint4* hhbuf;
    float *asrcb, *adstb, *out1b, *out2b, *gateb;
    cudaGetSymbolAddress((void**)&x16b,  g_x16);
    cudaGetSymbolAddress((void**)&w1hb,  g_w1h);
    cudaGetSymbolAddress((void**)&w2hb,  g_w2h);
    cudaGetSymbolAddress((void**)&o16b,  g_o16);
    cudaGetSymbolAddress((void**)&hhbuf, g_hh);
    cudaGetSymbolAddress((void**)&asrcb, g_asrc);
    cudaGetSymbolAddress((void**)&adstb, g_adst);
    cudaGetSymbolAddress((void**)&out1b, g_out1);
    cudaGetSymbolAddress((void**)&out2b, g_out2);
    cudaGetSymbolAddress((void**)&gateb, g_gate);

    int nb = (N + SCAN_BS - 1) / SCAN_BS;

    // CSR build + conversions
    prep_kernel<<<(N + 255) / 256, 256>>>((const long long*)ei, W1, W2, N);
    int x8 = N * 128 / 8;
    xcvt_kernel<<<(x8 + 255) / 256, 256>>>(x, x8);
    int convT = 2 * E + N;
    convert_kernel<<<(convT + 255) / 256, 256>>>(ei, bt, E, N);
    scan1_kernel<<<nb, SCAN_BS>>>(N);
    scan2_kernel<<<1, 1024>>>(nb);
    scan3_kernel<<<(N + 255) / 256, 256>>>(N, E);
    scatter_kernel<<<(E + N + 255) / 256, 256>>>(E, N);

    dim3 ggrid(4, NPAD / 64);
    int wblocks = (N + 7) / 8;

    // layer 1: tensor-core GEMM (+ fused scores), then aggregate
    gemm_attn_kernel<<<ggrid, 128>>>(x16b, w1hb, hhbuf, as1, ad1, asrcb, adstb, 128);
    aggregate_kernel<<<wblocks, 256>>>(hhbuf, asrcb, adstb, b1, out1b, (uint4*)o16b, N);

    // layer 2
    gemm_attn_kernel<<<ggrid, 128>>>(o16b, w2hb, hhbuf, as2, ad2, asrcb, adstb, 64);
    aggregate_kernel<<<wblocks, 256>>>(hhbuf, asrcb, adstb, b2, out2b, (uint4*)o16b, N);

    // pooling
    gate_kernel<<<(N + 63) / 64, 64>>>(out2b, gw1, gb1, gam, bet, gw2, gb2, gateb, N);
    gptr_kernel<<<(N + 255) / 256, 256>>>(N);
    pool_kernel<<<GNUM, 256>>>(out2b, N);
    final_kernel<<<1, 64>>>(lw, lb, (float*)d_out);
}

// round 7
// speedup vs baseline: 1.4620x; 1.1176x over previous
#include <cuda_runtime.h>
#include <cuda_fp16.h>
#include <mma.h>
#include <math.h>
#include <stdint.h>

using namespace nvcuda;

#define NNODES 50000
#define NPAD   50048
#define NEDGES 800000
#define TOTE   (NEDGES + NNODES)
#define GNUM   64
#define NEG_SLOPE 0.2f
#define CSRB   ((NNODES + 255) / 256)   // 196 blocks, all resident

// ---------------- static device scratch ----------------
static __device__ int      g_is64;
static __device__ unsigned g_barcnt;
static __device__ unsigned g_bargen;
static __device__ int    g_src[NEDGES];
static __device__ int    g_dst[NEDGES];
static __device__ int    g_batch[NNODES];
static __device__ int    g_deg[NNODES];
static __device__ int    g_row[NNODES + 1];
static __device__ int    g_cur[NNODES];
static __device__ int    g_col[TOTE];
static __device__ int    g_bsum[CSRB];
static __device__ int    g_gptr[GNUM + 1];
static __device__ __half g_x16[(size_t)NPAD * 128];
static __device__ __half g_w1h[128 * 256];
static __device__ __half g_w2h[64 * 256];
static __device__ __half g_gw1h[64 * 64];
static __device__ __half g_o16[(size_t)NPAD * 64];
static __device__ uint4  g_hh[(size_t)NPAD * 32];
static __device__ float  g_asrc[NPAD * 4];
static __device__ float  g_adst[NPAD * 4];
static __device__ float  g_out1[(size_t)NNODES * 64];
static __device__ float  g_out2[(size_t)NNODES * 64];
static __device__ float  g_gate[NNODES];

// ---------------- prep: zero deg, detect dtype, fp16 weights, fp16 x ----------------
__global__ void prep_kernel(const long long* __restrict__ ei,
                            const float* __restrict__ x,
                            const float* __restrict__ W1,
                            const float* __restrict__ W2,
                            const float* __restrict__ gw1,
                            int N, int total8) {
    int i = blockIdx.x * blockDim.x + threadIdx.x;
    if (i < N) g_deg[i] = 0;
    if (i < 128 * 256) g_w1h[i] = __float2half(W1[i]);
    if (i < 64 * 256)  g_w2h[i] = __float2half(W2[i]);
    if (i < 64 * 64)   g_gw1h[i] = __float2half(gw1[i]);
    if (i < total8) {
        float4 a = ((const float4*)x)[2 * i];
        float4 b = ((const float4*)x)[2 * i + 1];
        __half h8[8] = {__float2half(a.x), __float2half(a.y), __float2half(a.z), __float2half(a.w),
                        __float2half(b.x), __float2half(b.y), __float2half(b.z), __float2half(b.w)};
        ((uint4*)g_x16)[i] = *(uint4*)h8;
    }
    if (blockIdx.x == 0 && threadIdx.x < 32) {
        long long v = ei[threadIdx.x];
        int ok = (v >= 0 && v < (long long)N);
        unsigned all = __all_sync(0xFFFFFFFFu, ok);
        if (threadIdx.x == 0) g_is64 = all ? 1 : 0;
    }
}

// ---------------- convert indices + batch + fused degree ----------------
__global__ void convert_kernel(const void* __restrict__ ei, const void* __restrict__ bt,
                               int E, int N) {
    int i = blockIdx.x * blockDim.x + threadIdx.x;
    int total = 2 * E + N;
    if (i >= total) return;
    int is64 = g_is64;
    if (i < 2 * E) {
        int v = is64 ? (int)((const long long*)ei)[i] : ((const int*)ei)[i];
        if (i < E) g_src[i] = v;
        else { g_dst[i - E] = v; atomicAdd(&g_deg[v], 1); }
    } else {
        int j = i - 2 * E;
        int v = is64 ? (int)((const long long*)bt)[j] : ((const int*)bt)[j];
        g_batch[j] = v;
    }
}

// ---------------- fused CSR: scan + offsets + scatter (grid barriers) ----------------
__device__ __forceinline__ void grid_barrier(int nblocks) {
    __threadfence();
    __syncthreads();
    if (threadIdx.x == 0) {
        unsigned gen = atomicAdd(&g_bargen, 0u);
        unsigned prev = atomicAdd(&g_barcnt, 1u);
        if (prev == (unsigned)(nblocks - 1)) {
            atomicExch(&g_barcnt, 0u);
            __threadfence();
            atomicAdd(&g_bargen, 1u);
        } else {
            while (atomicAdd(&g_bargen, 0u) == gen) { }
        }
    }
    __syncthreads();
}

__global__ void __launch_bounds__(256) csr_kernel(int N, int E) {
    __shared__ int ws[8];
    __shared__ int red[32];
    int tid = threadIdx.x, lane = tid & 31, wid = tid >> 5;
    int bid = blockIdx.x;
    int i = bid * 256 + tid;

    // phase 1: block-local exclusive scan of deg+1
    int x = (i < N) ? g_deg[i] + 1 : 0;
    int v = x;
    #pragma unroll
    for (int o = 1; o < 32; o <<= 1) {
        int u = __shfl_up_sync(0xFFFFFFFFu, v, o);
        if (lane >= o) v += u;
    }
    if (lane == 31) ws[wid] = v;
    __syncthreads();
    if (wid == 0) {
        int w = (lane < 8) ? ws[lane] : 0;
        #pragma unroll
        for (int o = 1; o < 8; o <<= 1) {
            int u = __shfl_up_sync(0xFFFFFFFFu, w, o);
            if (lane >= o) w += u;
        }
        if (lane < 8) ws[lane] = w;
    }
    __syncthreads();
    int incl = v + (wid ? ws[wid - 1] : 0);
    if (tid == 255) g_bsum[bid] = incl;

    grid_barrier(CSRB);

    // phase 2: each block independently reduces bsum[0..bid)
    int part = (tid < bid) ? g_bsum[tid] : 0;   // bid < 256 always
    #pragma unroll
    for (int o = 16; o; o >>= 1) part += __shfl_xor_sync(0xFFFFFFFFu, part, o);
    if (lane == 0) red[wid] = part;
    __syncthreads();
    int off;
    {
        int t = (lane < 8) ? red[lane] : 0;
        #pragma unroll
        for (int o = 4; o; o >>= 1) t += __shfl_xor_sync(0xFFFFFFFFu, t, o);
        off = __shfl_sync(0xFFFFFFFFu, t, 0);
    }
    int r = incl - x + off;
    if (i < N) { g_row[i] = r; g_cur[i] = r; }
    if (i == 0) g_row[N] = E + N;

    grid_barrier(CSRB);

    // phase 3: scatter edges + self-loops
    for (int e = bid * 256 + tid; e < E + N; e += CSRB * 256) {
        int s, d;
        if (e < E) { s = g_src[e]; d = g_dst[e]; }
        else       { s = d = e - E; }
        int pos = atomicAdd(&g_cur[d], 1);
        g_col[pos] = s;
    }
}

// ---------------- tensor-core GEMM + fused attention-score epilogue ----------------
__global__ void __launch_bounds__(128) gemm_attn_kernel(const __half* __restrict__ A,
                                                        const __half* __restrict__ B,
                                                        uint4* __restrict__ C,
                                                        const float* __restrict__ att_src,
                                                        const float* __restrict__ att_dst,
                                                        float* __restrict__ asrc,
                                                        float* __restrict__ adst,
                                                        int K) {
    __shared__ float Cs[64 * 68];
    int tid = threadIdx.x;
    int warp = tid >> 5;
    int bx = blockIdx.x;       // head
    int by = blockIdx.y;       // 64-row tile
    int row0 = by * 64 + warp * 16;

    wmma::fragment<wmma::accumulator, 16, 16, 16, float> cf[4];
    #pragma unroll
    for (int n = 0; n < 4; n++) wmma::fill_fragment(cf[n], 0.f);

    for (int k0 = 0; k0 < K; k0 += 16) {
        wmma::fragment<wmma::matrix_a, 16, 16, 16, __half, wmma::row_major> af;
        wmma::load_matrix_sync(af, A + (size_t)row0 * K + k0, K);
        #pragma unroll
        for (int n = 0; n < 4; n++) {
            wmma::fragment<wmma::matrix_b, 16, 16, 16, __half, wmma::row_major> bf;
            wmma::load_matrix_sync(bf, B + (size_t)k0 * 256 + bx * 64 + n * 16, 256);
            wmma::mma_sync(cf[n], af, bf, cf[n]);
        }
    }
    #pragma unroll
    for (int n = 0; n < 4; n++)
        wmma::store_matrix_sync(Cs + warp * 16 * 68 + n * 16, cf[n], 68, wmma::mem_row_major);
    __syncthreads();

    int r = tid >> 1;
    int ch = (tid & 1) * 32;
    int row = by * 64 + r;
    float s = 0.f, d = 0.f;
    __half h16[32];
    #pragma unroll
    for (int c = 0; c < 32; c++) {
        float v = Cs[r * 68 + ch + c];
        s += v * __ldg(att_src + bx * 64 + ch + c);
        d += v * __ldg(att_dst + bx * 64 + ch + c);
        h16[c] = __float2half(v);
    }
    uint4* dst = C + (size_t)row * 32 + bx * 8 + (ch >> 3);
    uint4* src = (uint4*)h16;
    #pragma unroll
    for (int q = 0; q < 4; q++) dst[q] = src[q];
    s += __shfl_xor_sync(0xFFFFFFFFu, s, 1);
    d += __shfl_xor_sync(0xFFFFFFFFu, d, 1);
    if ((tid & 1) == 0) {
        asrc[row * 4 + bx] = s;
        adst[row * 4 + bx] = d;
    }
}

// ---------------- GAT aggregation: chunked smem-broadcast, gather-only inner loop ----------------
__device__ __forceinline__ void fma_half8(float* a, uint4 v, float w) {
    __half2* p = (__half2*)&v;
    #pragma unroll
    for (int q = 0; q < 4; q++) {
        float2 f = __half22float2(p[q]);
        a[2 * q]     += w * f.x;
        a[2 * q + 1] += w * f.y;
    }
}

__device__ __forceinline__ float lrelu(float e) { return (e > 0.f) ? e : NEG_SLOPE * e; }

__global__ void __launch_bounds__(256) aggregate_kernel(const uint4* __restrict__ hh,
                                                        const float* __restrict__ asrc,
                                                        const float* __restrict__ adst,
                                                        const float* __restrict__ bias,
                                                        float* __restrict__ out,
                                                        uint4* __restrict__ out16,
                                                        int N) {
    __shared__ int   ss[8][32];
    __shared__ float swt[8][4][32];
    int gw = (blockIdx.x * blockDim.x + threadIdx.x) >> 5;   // node
    if (gw >= N) return;
    int wslot = (threadIdx.x >> 5);
    int lane = threadIdx.x & 31;
    int start = g_row[gw], end = g_row[gw + 1];
    int deg = end - start;
    float4 ad = *(const float4*)(adst + 4 * gw);
    int head = lane >> 3;

    float acc0[8], acc1[8];
    #pragma unroll
    for (int k = 0; k < 8; k++) { acc0[k] = 0.f; acc1[k] = 0.f; }
    float den = 0.f;

    if (deg <= 32) {
        // fast path: single chunk, fused max
        int myj = start + lane;
        int mys = 0;
        float e0 = -1e30f, e1 = -1e30f, e2 = -1e30f, e3 = -1e30f;
        if (myj < end) {
            mys = g_col[myj];
            float4 q = *(const float4*)(asrc + 4 * mys);
            e0 = lrelu(q.x + ad.x); e1 = lrelu(q.y + ad.y);
            e2 = lrelu(q.z + ad.z); e3 = lrelu(q.w + ad.w);
        }
        float m0 = e0, m1 = e1, m2 = e2, m3 = e3;
        #pragma unroll
        for (int o = 16; o; o >>= 1) {
            m0 = fmaxf(m0, __shfl_xor_sync(0xFFFFFFFFu, m0, o));
            m1 = fmaxf(m1, __shfl_xor_sync(0xFFFFFFFFu, m1, o));
            m2 = fmaxf(m2, __shfl_xor_sync(0xFFFFFFFFu, m2, o));
            m3 = fmaxf(m3, __shfl_xor_sync(0xFFFFFFFFu, m3, o));
        }
        ss[wslot][lane] = mys;
        swt[wslot][0][lane] = (myj < end) ? expf(e0 - m0) : 0.f;
        swt[wslot][1][lane] = (myj < end) ? expf(e1 - m1) : 0.f;
        swt[wslot][2][lane] = (myj < end) ? expf(e2 - m2) : 0.f;
        swt[wslot][3][lane] = (myj < end) ? expf(e3 - m3) : 0.f;
        __syncwarp();
        int j = 0;
        for (; j + 4 <= deg; j += 4) {
            int s0 = ss[wslot][j], s1 = ss[wslot][j + 1];
            int s2 = ss[wslot][j + 2], s3 = ss[wslot][j + 3];
            float w0 = swt[wslot][head][j],     w1 = swt[wslot][head][j + 1];
            float w2 = swt[wslot][head][j + 2], w3 = swt[wslot][head][j + 3];
            uint4 v0 = hh[(size_t)s0 * 32 + lane];
            uint4 v1 = hh[(size_t)s1 * 32 + lane];
            uint4 v2 = hh[(size_t)s2 * 32 + lane];
            uint4 v3 = hh[(size_t)s3 * 32 + lane];
            den += (w0 + w1) + (w2 + w3);
            fma_half8(acc0, v0, w0);
            fma_half8(acc1, v1, w1);
            fma_half8(acc0, v2, w2);
            fma_half8(acc1, v3, w3);
        }
        for (; j < deg; j++) {
            int s0 = ss[wslot][j];
            float w0 = swt[wslot][head][j];
            uint4 v0 = hh[(size_t)s0 * 32 + lane];
            den += w0;
            fma_half8(acc0, v0, w0);
        }
        __syncwarp();
    } else {
        // general path: pass 1 max, then chunked pass 2
        float m0 = -1e30f, m1 = -1e30f, m2 = -1e30f, m3 = -1e30f;
        for (int j = start + lane; j < end; j += 32) {
            int s = g_col[j];
            float4 q = *(const float4*)(asrc + 4 * s);
            m0 = fmaxf(m0, lrelu(q.x + ad.x));
            m1 = fmaxf(m1, lrelu(q.y + ad.y));
            m2 = fmaxf(m2, lrelu(q.z + ad.z));
            m3 = fmaxf(m3, lrelu(q.w + ad.w));
        }
        #pragma unroll
        for (int o = 16; o; o >>= 1) {
            m0 = fmaxf(m0, __shfl_xor_sync(0xFFFFFFFFu, m0, o));
            m1 = fmaxf(m1, __shfl_xor_sync(0xFFFFFFFFu, m1, o));
            m2 = fmaxf(m2, __shfl_xor_sync(0xFFFFFFFFu, m2, o));
            m3 = fmaxf(m3, __shfl_xor_sync(0xFFFFFFFFu, m3, o));
        }
        for (int base = start; base < end; base += 32) {
            int nn = min(32, end - base);
            int myj = base + lane;
            int mys = 0;
            float w0v = 0.f, w1v = 0.f, w2v = 0.f, w3v = 0.f;
            if (myj < end) {
                mys = g_col[myj];
                float4 q = *(const float4*)(asrc + 4 * mys);
                w0v = expf(lrelu(q.x + ad.x) - m0);
                w1v = expf(lrelu(q.y + ad.y) - m1);
                w2v = expf(lrelu(q.z + ad.z) - m2);
                w3v = expf(lrelu(q.w + ad.w) - m3);
            }
            ss[wslot][lane] = mys;
            swt[wslot][0][lane] = w0v;
            swt[wslot][1][lane] = w1v;
            swt[wslot][2][lane] = w2v;
            swt[wslot][3][lane] = w3v;
            __syncwarp();
            int j = 0;
            for (; j + 4 <= nn; j += 4) {
                int s0 = ss[wslot][j], s1 = ss[wslot][j + 1];
                int s2 = ss[wslot][j + 2], s3 = ss[wslot][j + 3];
                float w0 = swt[wslot][head][j],     w1 = swt[wslot][head][j + 1];
                float w2 = swt[wslot][head][j + 2], w3 = swt[wslot][head][j + 3];
                uint4 v0 = hh[(size_t)s0 * 32 + lane];
                uint4 v1 = hh[(size_t)s1 * 32 + lane];
                uint4 v2 = hh[(size_t)s2 * 32 + lane];
                uint4 v3 = hh[(size_t)s3 * 32 + lane];
                den += (w0 + w1) + (w2 + w3);
                fma_half8(acc0, v0, w0);
                fma_half8(acc1, v1, w1);
                fma_half8(acc0, v2, w2);
                fma_half8(acc1, v3, w3);
            }
            for (; j < nn; j++) {
                int s0 = ss[wslot][j];
                float w0 = swt[wslot][head][j];
                uint4 v0 = hh[(size_t)s0 * 32 + lane];
                den += w0;
                fma_half8(acc0, v0, w0);
            }
            __syncwarp();
        }
    }

    float inv = 1.f / (den + 1e-16f);
    float r[8];
    #pragma unroll
    for (int k = 0; k < 8; k++) r[k] = (acc0[k] + acc1[k]) * inv;
    #pragma unroll
    for (int k = 0; k < 8; ++k) {
        r[k] += __shfl_xor_sync(0xFFFFFFFFu, r[k], 8);
        r[k] += __shfl_xor_sync(0xFFFFFFFFu, r[k], 16);
    }
    if (lane < 8) {
        float o_[8];
        __half h8[8];
        #pragma unroll
        for (int k = 0; k < 8; ++k) {
            float v = 0.25f * r[k] + bias[lane * 8 + k];
            float sg = 1.f / (1.f + expf(-v));
            o_[k] = sg;
            h8[k] = __float2half(sg);
        }
        float4* op = (float4*)(out + (size_t)gw * 64 + lane * 8);
        op[0] = make_float4(o_[0], o_[1], o_[2], o_[3]);
        op[1] = make_float4(o_[4], o_[5], o_[6], o_[7]);
        out16[(size_t)gw * 8 + lane] = *(uint4*)h8;
    }
}

// ---------------- gate via wmma: g[v] = relu(bn(o16@gw1+gb1)) @ gw2 + gb2 ----------------
__global__ void __launch_bounds__(128) gate_wmma_kernel(const __half* __restrict__ A,
                                                        const __half* __restrict__ B,
                                                        const float* __restrict__ gb1,
                                                        const float* __restrict__ gamma,
                                                        const float* __restrict__ beta,
                                                        const float* __restrict__ gw2,
                                                        const float* __restrict__ gb2,
                                                        float* __restrict__ gout, int N) {
    __shared__ float Cs[64 * 68];
    int tid = threadIdx.x;
    int warp = tid >> 5;
    int by = blockIdx.x;
    int row0 = by * 64 + warp * 16;

    wmma::fragment<wmma::accumulator, 16, 16, 16, float> cf[4];
    #pragma unroll
    for (int n = 0; n < 4; n++) wmma::fill_fragment(cf[n], 0.f);
    for (int k0 = 0; k0 < 64; k0 += 16) {
        wmma::fragment<wmma::matrix_a, 16, 16, 16, __half, wmma::row_major> af;
        wmma::load_matrix_sync(af, A + (size_t)row0 * 64 + k0, 64);
        #pragma unroll
        for (int n = 0; n < 4; n++) {
            wmma::fragment<wmma::matrix_b, 16, 16, 16, __half, wmma::row_major> bf;
            wmma::load_matrix_sync(bf, B + (size_t)k0 * 64 + n * 16, 64);
            wmma::mma_sync(cf[n], af, bf, cf[n]);
        }
    }
    #pragma unroll
    for (int n = 0; n < 4; n++)
        wmma::store_matrix_sync(Cs + warp * 16 * 68 + n * 16, cf[n], 68, wmma::mem_row_major);
    __syncthreads();

    int r = tid >> 1;
    int ch = (tid & 1) * 32;
    int row = by * 64 + r;
    float kinv = rsqrtf(1.0f + 1e-5f);
    float s = 0.f;
    #pragma unroll
    for (int c = 0; c < 32; c++) {
        float t = (Cs[r * 68 + ch + c] + __ldg(gb1 + ch + c)) * kinv * __ldg(gamma + ch + c)
                  + __ldg(beta + ch + c);
        t = fmaxf(t, 0.f);
        s += t * __ldg(gw2 + ch + c);
    }
    s += __shfl_xor_sync(0xFFFFFFFFu, s, 1);
    if ((tid & 1) == 0 && row < N) gout[row] = s + gb2[0];
}

// ---------------- per-graph boundaries (batch sorted) ----------------
__global__ void gptr_kernel(int N) {
    int v = blockIdx.x * blockDim.x + threadIdx.x;
    if (v >= N) return;
    int b = g_batch[v];
    if (v == 0) {
        for (int i = 0; i <= b; i++) g_gptr[i] = 0;
    } else {
        int bp = g_batch[v - 1];
        for (int i = bp + 1; i <= b; i++) g_gptr[i] = v;
    }
    if (v == N - 1) {
        for (int i = b + 1; i <= GNUM; i++) g_gptr[i] = N;
    }
}

// ---------------- pooling + final, fused ----------------
__global__ void __launch_bounds__(256) pool_kernel(const float* __restrict__ out2,
                                                   const float* __restrict__ lw,
                                                   const float* __restrict__ lb,
                                                   float* __restrict__ result, int N) {
    int b = blockIdx.x;
    int start = g_gptr[b], end = g_gptr[b + 1];
    __shared__ float smax[256];
    __shared__ float sacc[256];
    __shared__ float sden[4];
    int tid = threadIdx.x;
    float m = -1e30f;
    for (int v = start + tid; v < end; v += 256) m = fmaxf(m, g_gate[v]);
    smax[tid] = m;
    __syncthreads();
    for (int s = 128; s; s >>= 1) {
        if (tid < s) smax[tid] = fmaxf(smax[tid], smax[tid + s]);
        __syncthreads();
    }
    float mx = smax[0];
    __syncthreads();
    int c = tid & 63;
    int sub = tid >> 6;
    float acc = 0.f, dacc = 0.f;
    for (int v = start + sub; v < end; v += 4) {
        float w = expf(g_gate[v] - mx);
        acc += w * out2[(size_t)v * 64 + c];
        if (c == 0) dacc += w;
    }
    sacc[tid] = acc;
    if (c == 0) sden[sub] = dacc;
    __syncthreads();
    if (sub == 0) {
        float p = sacc[c] + sacc[64 + c] + sacc[128 + c] + sacc[192 + c];
        sacc[c] = p * __ldg(lw + c);
    }
    __syncthreads();
    if (tid < 32) {
        float t = sacc[tid] + sacc[tid + 32];
        #pragma unroll
        for (int o = 16; o; o >>= 1) t += __shfl_xor_sync(0xFFFFFFFFu, t, o);
        if (tid == 0) {
            float dt = sden[0] + sden[1] + sden[2] + sden[3];
            float s = t / (dt + 1e-16f) + lb[0];
            result[b] = 1.f / (1.f + expf(-s));
        }
    }
}

// ---------------- launch ----------------
extern "C" void kernel_launch(void* const* d_in, const int* in_sizes, int n_in,
                              void* d_out, int out_size) {
    const float* x  = (const float*)d_in[0];
    const void*  ei = d_in[1];
    const void*  bt = d_in[2];
    int o = (in_sizes[3] == 1) ? 1 : 0;
    const float* W1  = (const float*)d_in[3 + o];
    const float* as1 = (const float*)d_in[4 + o];
    const float* ad1 = (const float*)d_in[5 + o];
    const float* b1  = (const float*)d_in[6 + o];
    const float* W2  = (const float*)d_in[7 + o];
    const float* as2 = (const float*)d_in[8 + o];
    const float* ad2 = (const float*)d_in[9 + o];
    const float* b2  = (const float*)d_in[10 + o];
    const float* gw1 = (const float*)d_in[11 + o];
    const float* gb1 = (const float*)d_in[12 + o];
    const float* gam = (const float*)d_in[13 + o];
    const float* bet = (const float*)d_in[14 + o];
    const float* gw2 = (const float*)d_in[15 + o];
    const float* gb2 = (const float*)d_in[16 + o];
    const float* lw  = (const float*)d_in[17 + o];
    const float* lb  = (const float*)d_in[18 + o];

    int N = in_sizes[0] / 128;
    int E = in_sizes[1] / 2;

    __half *x16b, *w1hb, *w2hb, *gw1hb, *o16b;
    uint4* hhbuf;
    float *asrcb, *adstb, *out1b, *out2b, *gateb;
    cudaGetSymbolAddress((void**)&x16b,  g_x16);
    cudaGetSymbolAddress((void**)&w1hb,  g_w1h);
    cudaGetSymbolAddress((void**)&w2hb,  g_w2h);
    cudaGetSymbolAddress((void**)&gw1hb, g_gw1h);
    cudaGetSymbolAddress((void**)&o16b,  g_o16);
    cudaGetSymbolAddress((void**)&hhbuf, g_hh);
    cudaGetSymbolAddress((void**)&asrcb, g_asrc);
    cudaGetSymbolAddress((void**)&adstb, g_adst);
    cudaGetSymbolAddress((void**)&out1b, g_out1);
    cudaGetSymbolAddress((void**)&out2b, g_out2);
    cudaGetSymbolAddress((void**)&gateb, g_gate);

    int x8 = N * 128 / 8;
    int prepT = (x8 > 128 * 256) ? x8 : 128 * 256;

    // 0: prep (deg zero, dtype detect, weight + x fp16)
    prep_kernel<<<(prepT + 255) / 256, 256>>>((const long long*)ei, x, W1, W2, gw1, N, x8);
    // 1: convert (indices + batch + degree)
    int convT = 2 * E + N;
    convert_kernel<<<(convT + 255) / 256, 256>>>(ei, bt, E, N);
    // 2: fused CSR (scan + scatter)
    csr_kernel<<<CSRB, 256>>>(N, E);
    // 3: layer-1 GEMM (profiled slot)
    dim3 ggrid(4, NPAD / 64);
    gemm_attn_kernel<<<ggrid, 128>>>(x16b, w1hb, hhbuf, as1, ad1, asrcb, adstb, 128);
    // 4: layer-1 aggregate
    int wblocks = (N + 7) / 8;
    aggregate_kernel<<<wblocks, 256>>>(hhbuf, asrcb, adstb, b1, out1b, (uint4*)o16b, N);
    // 5-6: layer 2
    gemm_attn_kernel<<<ggrid, 128>>>(o16b, w2hb, hhbuf, as2, ad2, asrcb, adstb, 64);
    aggregate_kernel<<<wblocks, 256>>>(hhbuf, asrcb, adstb, b2, out2b, (uint4*)o16b, N);
    // 7-9: gate, graph boundaries, pool+final
    gate_wmma_kernel<<<NPAD / 64, 128>>>(o16b, gw1hb, gb1, gam, bet, gw2, gb2, gateb, N);
    gptr_kernel<<<(N + 255) / 256, 256>>>(N);
    pool_kernel<<<GNUM, 256>>>(out2b, lw, lb, (float*)d_out, N);
}

// round 8
// speedup vs baseline: 1.6857x; 1.1530x over previous
#include <cuda_runtime.h>
#include <cuda_fp16.h>
#include <mma.h>
#include <math.h>
#include <stdint.h>

using namespace nvcuda;

#define NNODES 50000
#define NPAD   50048
#define NEDGES 800000
#define TOTE   (NEDGES + NNODES)
#define GNUM   64
#define NEG_SLOPE 0.2f
#define CSRB   ((NNODES + 255) / 256)   // 196 blocks, all resident

// ---------------- static device scratch ----------------
static __device__ int      g_is64;
static __device__ unsigned g_barcnt;
static __device__ unsigned g_bargen;
static __device__ int    g_src[NEDGES];
static __device__ int    g_dst[NEDGES];
static __device__ int    g_batch[NNODES];
static __device__ int    g_deg[NNODES];
static __device__ int    g_row[NNODES + 1];
static __device__ int    g_cur[NNODES];
static __device__ int    g_col[TOTE];
static __device__ int    g_bsum[CSRB];
static __device__ int    g_gptr[GNUM + 1];
static __device__ __half g_x16[(size_t)NPAD * 128];
static __device__ __half g_w1h[128 * 256];
static __device__ __half g_w2h[64 * 256];
static __device__ __half g_gw1h[64 * 64];
static __device__ __half g_o16[(size_t)NPAD * 64];
static __device__ uint4  g_hh[(size_t)NPAD * 32];
static __device__ float  g_asrc[NPAD * 4];
static __device__ float  g_adst[NPAD * 4];
static __device__ float  g_out1[(size_t)NNODES * 64];
static __device__ float  g_out2[(size_t)NNODES * 64];
static __device__ float  g_gate[NNODES];

// ---------------- prep: zero deg, detect dtype, fp16 weights, fp16 x ----------------
__global__ void prep_kernel(const long long* __restrict__ ei,
                            const float* __restrict__ x,
                            const float* __restrict__ W1,
                            const float* __restrict__ W2,
                            const float* __restrict__ gw1,
                            int N, int total8) {
    int i = blockIdx.x * blockDim.x + threadIdx.x;
    if (i < N) g_deg[i] = 0;
    if (i < 128 * 256) g_w1h[i] = __float2half(W1[i]);
    if (i < 64 * 256)  g_w2h[i] = __float2half(W2[i]);
    if (i < 64 * 64)   g_gw1h[i] = __float2half(gw1[i]);
    if (i < total8) {
        float4 a = ((const float4*)x)[2 * i];
        float4 b = ((const float4*)x)[2 * i + 1];
        __half h8[8] = {__float2half(a.x), __float2half(a.y), __float2half(a.z), __float2half(a.w),
                        __float2half(b.x), __float2half(b.y), __float2half(b.z), __float2half(b.w)};
        ((uint4*)g_x16)[i] = *(uint4*)h8;
    }
    if (blockIdx.x == 0 && threadIdx.x < 32) {
        long long v = ei[threadIdx.x];
        int ok = (v >= 0 && v < (long long)N);
        unsigned all = __all_sync(0xFFFFFFFFu, ok);
        if (threadIdx.x == 0) g_is64 = all ? 1 : 0;
    }
}

// ---------------- convert indices + batch + fused degree ----------------
__global__ void convert_kernel(const void* __restrict__ ei, const void* __restrict__ bt,
                               int E, int N) {
    int i = blockIdx.x * blockDim.x + threadIdx.x;
    int total = 2 * E + N;
    if (i >= total) return;
    int is64 = g_is64;
    if (i < 2 * E) {
        int v = is64 ? (int)((const long long*)ei)[i] : ((const int*)ei)[i];
        if (i < E) g_src[i] = v;
        else { g_dst[i - E] = v; atomicAdd(&g_deg[v], 1); }
    } else {
        int j = i - 2 * E;
        int v = is64 ? (int)((const long long*)bt)[j] : ((const int*)bt)[j];
        g_batch[j] = v;
    }
}

// ---------------- fused CSR: scan + offsets + scatter (grid barriers) ----------------
__device__ __forceinline__ void grid_barrier(int nblocks) {
    __threadfence();
    __syncthreads();
    if (threadIdx.x == 0) {
        unsigned gen = atomicAdd(&g_bargen, 0u);
        unsigned prev = atomicAdd(&g_barcnt, 1u);
        if (prev == (unsigned)(nblocks - 1)) {
            atomicExch(&g_barcnt, 0u);
            __threadfence();
            atomicAdd(&g_bargen, 1u);
        } else {
            while (atomicAdd(&g_bargen, 0u) == gen) { }
        }
    }
    __syncthreads();
}

__global__ void __launch_bounds__(256) csr_kernel(int N, int E) {
    __shared__ int ws[8];
    __shared__ int red[32];
    int tid = threadIdx.x, lane = tid & 31, wid = tid >> 5;
    int bid = blockIdx.x;
    int i = bid * 256 + tid;

    int x = (i < N) ? g_deg[i] + 1 : 0;
    int v = x;
    #pragma unroll
    for (int o = 1; o < 32; o <<= 1) {
        int u = __shfl_up_sync(0xFFFFFFFFu, v, o);
        if (lane >= o) v += u;
    }
    if (lane == 31) ws[wid] = v;
    __syncthreads();
    if (wid == 0) {
        int w = (lane < 8) ? ws[lane] : 0;
        #pragma unroll
        for (int o = 1; o < 8; o <<= 1) {
            int u = __shfl_up_sync(0xFFFFFFFFu, w, o);
            if (lane >= o) w += u;
        }
        if (lane < 8) ws[lane] = w;
    }
    __syncthreads();
    int incl = v + (wid ? ws[wid - 1] : 0);
    if (tid == 255) g_bsum[bid] = incl;

    grid_barrier(CSRB);

    int part = (tid < bid) ? g_bsum[tid] : 0;
    #pragma unroll
    for (int o = 16; o; o >>= 1) part += __shfl_xor_sync(0xFFFFFFFFu, part, o);
    if (lane == 0) red[wid] = part;
    __syncthreads();
    int off;
    {
        int t = (lane < 8) ? red[lane] : 0;
        #pragma unroll
        for (int o = 4; o; o >>= 1) t += __shfl_xor_sync(0xFFFFFFFFu, t, o);
        off = __shfl_sync(0xFFFFFFFFu, t, 0);
    }
    int r = incl - x + off;
    if (i < N) { g_row[i] = r; g_cur[i] = r; }
    if (i == 0) g_row[N] = E + N;

    grid_barrier(CSRB);

    for (int e = bid * 256 + tid; e < E + N; e += CSRB * 256) {
        int s, d;
        if (e < E) { s = g_src[e]; d = g_dst[e]; }
        else       { s = d = e - E; }
        int pos = atomicAdd(&g_cur[d], 1);
        g_col[pos] = s;
    }
}

// ---------------- smem-staged tensor-core GEMM + fused attention-score epilogue ----------------
// Block: 256 thr (8 warps), 64 rows x 256 cols. A staged fully; B streamed in 32-k chunks.
// Warp w: rows (w>>1)*16..+16, col half (w&1)*128 -> 8 fragments of 16x16.
#define SM_AS_BYTES 17408                 // 64 * 136 halves (K=128 worst case)
#define SM_BS_BYTES 16896                 // 32 * 264 halves
__global__ void __launch_bounds__(256) gemm_attn_kernel(const __half* __restrict__ A,
                                                        const __half* __restrict__ B,
                                                        uint4* __restrict__ C,
                                                        const float* __restrict__ att_src,
                                                        const float* __restrict__ att_dst,
                                                        float* __restrict__ asrc,
                                                        float* __restrict__ adst,
                                                        int K) {
    __shared__ __align__(16) char smbuf[SM_AS_BYTES + SM_BS_BYTES];
    __half* As = (__half*)smbuf;                       // [64][K+8]
    __half* Bs = (__half*)(smbuf + SM_AS_BYTES);       // [32][264]
    float*  Cs = (float*)smbuf;                        // [64][132] (epilogue reuse)
    int tid = threadIdx.x;
    int warp = tid >> 5;
    int by = blockIdx.x;
    int lda = K + 8;
    int row0 = by * 64;

    // stage A tile (64 x K), coalesced uint4
    int kv = K >> 3;                 // uint4 per row
    int nA = 64 * kv;
    for (int i = tid; i < nA; i += 256) {
        int r = i / kv, c = i - r * kv;
        uint4 v = ((const uint4*)(A + (size_t)(row0 + r) * K))[c];
        *(uint4*)(As + r * lda + c * 8) = v;
    }

    int wr = warp >> 1;
    int wc = warp & 1;
    wmma::fragment<wmma::accumulator, 16, 16, 16, float> cf[8];
    #pragma unroll
    for (int n = 0; n < 8; n++) wmma::fill_fragment(cf[n], 0.f);

    for (int k0 = 0; k0 < K; k0 += 32) {
        __syncthreads();
        // stage B chunk (32 x 256)
        for (int i = tid; i < 1024; i += 256) {
            int r = i >> 5, c = i & 31;
            uint4 v = ((const uint4*)(B + (size_t)(k0 + r) * 256))[c];
            *(uint4*)(Bs + r * 264 + c * 8) = v;
        }
        __syncthreads();
        #pragma unroll
        for (int ks = 0; ks < 32; ks += 16) {
            wmma::fragment<wmma::matrix_a, 16, 16, 16, __half, wmma::row_major> af;
            wmma::load_matrix_sync(af, As + (wr * 16) * lda + k0 + ks, lda);
            #pragma unroll
            for (int n = 0; n < 8; n++) {
                wmma::fragment<wmma::matrix_b, 16, 16, 16, __half, wmma::row_major> bf;
                wmma::load_matrix_sync(bf, Bs + ks * 264 + wc * 128 + n * 16, 264);
                wmma::mma_sync(cf[n], af, bf, cf[n]);
            }
        }
    }

    // epilogue: two waves (col half each) through reused smem
    int er = tid >> 2;          // row 0..63
    int cseg = tid & 3;         // 32-col segment within the 128-col half
    #pragma unroll
    for (int wv = 0; wv < 2; wv++) {
        __syncthreads();
        if (wc == wv) {
            #pragma unroll
            for (int n = 0; n < 8; n++)
                wmma::store_matrix_sync(Cs + (wr * 16) * 132 + n * 16, cf[n], 132, wmma::mem_row_major);
        }
        __syncthreads();
        int gcol = wv * 128 + cseg * 32;
        int head = gcol >> 6;
        int hoff = gcol - head * 64;
        float s = 0.f, d = 0.f;
        __half h16[32];
        #pragma unroll
        for (int c = 0; c < 32; c++) {
            float v = Cs[er * 132 + cseg * 32 + c];
            s += v * __ldg(att_src + head * 64 + hoff + c);
            d += v * __ldg(att_dst + head * 64 + hoff + c);
            h16[c] = __float2half(v);
        }
        uint4* dst = C + (size_t)(row0 + er) * 32 + (gcol >> 3);
        uint4* srcp = (uint4*)h16;
        #pragma unroll
        for (int q = 0; q < 4; q++) dst[q] = srcp[q];
        s += __shfl_xor_sync(0xFFFFFFFFu, s, 1);
        d += __shfl_xor_sync(0xFFFFFFFFu, d, 1);
        if ((tid & 1) == 0) {
            asrc[(row0 + er) * 4 + head] = s;
            adst[(row0 + er) * 4 + head] = d;
        }
    }
}

// ---------------- GAT aggregation: chunked smem-broadcast, gather-only inner loop ----------------
__device__ __forceinline__ void fma_half8(float* a, uint4 v, float w) {
    __half2* p = (__half2*)&v;
    #pragma unroll
    for (int q = 0; q < 4; q++) {
        float2 f = __half22float2(p[q]);
        a[2 * q]     += w * f.x;
        a[2 * q + 1] += w * f.y;
    }
}

__device__ __forceinline__ float lrelu(float e) { return (e > 0.f) ? e : NEG_SLOPE * e; }

__global__ void __launch_bounds__(256) aggregate_kernel(const uint4* __restrict__ hh,
                                                        const float* __restrict__ asrc,
                                                        const float* __restrict__ adst,
                                                        const float* __restrict__ bias,
                                                        float* __restrict__ out,
                                                        uint4* __restrict__ out16,
                                                        int N) {
    __shared__ int   ss[8][32];
    __shared__ float swt[8][4][32];
    int gw = (blockIdx.x * blockDim.x + threadIdx.x) >> 5;
    if (gw >= N) return;
    int wslot = (threadIdx.x >> 5);
    int lane = threadIdx.x & 31;
    int start = g_row[gw], end = g_row[gw + 1];
    int deg = end - start;
    float4 ad = *(const float4*)(adst + 4 * gw);
    int head = lane >> 3;

    float acc0[8], acc1[8];
    #pragma unroll
    for (int k = 0; k < 8; k++) { acc0[k] = 0.f; acc1[k] = 0.f; }
    float den = 0.f;

    if (deg <= 32) {
        int myj = start + lane;
        int mys = 0;
        float e0 = -1e30f, e1 = -1e30f, e2 = -1e30f, e3 = -1e30f;
        if (myj < end) {
            mys = g_col[myj];
            float4 q = *(const float4*)(asrc + 4 * mys);
            e0 = lrelu(q.x + ad.x); e1 = lrelu(q.y + ad.y);
            e2 = lrelu(q.z + ad.z); e3 = lrelu(q.w + ad.w);
        }
        float m0 = e0, m1 = e1, m2 = e2, m3 = e3;
        #pragma unroll
        for (int o = 16; o; o >>= 1) {
            m0 = fmaxf(m0, __shfl_xor_sync(0xFFFFFFFFu, m0, o));
            m1 = fmaxf(m1, __shfl_xor_sync(0xFFFFFFFFu, m1, o));
            m2 = fmaxf(m2, __shfl_xor_sync(0xFFFFFFFFu, m2, o));
            m3 = fmaxf(m3, __shfl_xor_sync(0xFFFFFFFFu, m3, o));
        }
        ss[wslot][lane] = mys;
        swt[wslot][0][lane] = (myj < end) ? expf(e0 - m0) : 0.f;
        swt[wslot][1][lane] = (myj < end) ? expf(e1 - m1) : 0.f;
        swt[wslot][2][lane] = (myj < end) ? expf(e2 - m2) : 0.f;
        swt[wslot][3][lane] = (myj < end) ? expf(e3 - m3) : 0.f;
        __syncwarp();
        int j = 0;
        for (; j + 4 <= deg; j += 4) {
            int s0 = ss[wslot][j], s1 = ss[wslot][j + 1];
            int s2 = ss[wslot][j + 2], s3 = ss[wslot][j + 3];
            float w0 = swt[wslot][head][j],     w1 = swt[wslot][head][j + 1];
            float w2 = swt[wslot][head][j + 2], w3 = swt[wslot][head][j + 3];
            uint4 v0 = hh[(size_t)s0 * 32 + lane];
            uint4 v1 = hh[(size_t)s1 * 32 + lane];
            uint4 v2 = hh[(size_t)s2 * 32 + lane];
            uint4 v3 = hh[(size_t)s3 * 32 + lane];
            den += (w0 + w1) + (w2 + w3);
            fma_half8(acc0, v0, w0);
            fma_half8(acc1, v1, w1);
            fma_half8(acc0, v2, w2);
            fma_half8(acc1, v3, w3);
        }
        for (; j < deg; j++) {
            int s0 = ss[wslot][j];
            float w0 = swt[wslot][head][j];
            uint4 v0 = hh[(size_t)s0 * 32 + lane];
            den += w0;
            fma_half8(acc0, v0, w0);
        }
        __syncwarp();
    } else {
        float m0 = -1e30f, m1 = -1e30f, m2 = -1e30f, m3 = -1e30f;
        for (int j = start + lane; j < end; j += 32) {
            int s = g_col[j];
            float4 q = *(const float4*)(asrc + 4 * s);
            m0 = fmaxf(m0, lrelu(q.x + ad.x));
            m1 = fmaxf(m1, lrelu(q.y + ad.y));
            m2 = fmaxf(m2, lrelu(q.z + ad.z));
            m3 = fmaxf(m3, lrelu(q.w + ad.w));
        }
        #pragma unroll
        for (int o = 16; o; o >>= 1) {
            m0 = fmaxf(m0, __shfl_xor_sync(0xFFFFFFFFu, m0, o));
            m1 = fmaxf(m1, __shfl_xor_sync(0xFFFFFFFFu, m1, o));
            m2 = fmaxf(m2, __shfl_xor_sync(0xFFFFFFFFu, m2, o));
            m3 = fmaxf(m3, __shfl_xor_sync(0xFFFFFFFFu, m3, o));
        }
        for (int base = start; base < end; base += 32) {
            int nn = min(32, end - base);
            int myj = base + lane;
            int mys = 0;
            float w0v = 0.f, w1v = 0.f, w2v = 0.f, w3v = 0.f;
            if (myj < end) {
                mys = g_col[myj];
                float4 q = *(const float4*)(asrc + 4 * mys);
                w0v = expf(lrelu(q.x + ad.x) - m0);
                w1v = expf(lrelu(q.y + ad.y) - m1);
                w2v = expf(lrelu(q.z + ad.z) - m2);
                w3v = expf(lrelu(q.w + ad.w) - m3);
            }
            ss[wslot][lane] = mys;
            swt[wslot][0][lane] = w0v;
            swt[wslot][1][lane] = w1v;
            swt[wslot][2][lane] = w2v;
            swt[wslot][3][lane] = w3v;
            __syncwarp();
            int j = 0;
            for (; j + 4 <= nn; j += 4) {
                int s0 = ss[wslot][j], s1 = ss[wslot][j + 1];
                int s2 = ss[wslot][j + 2], s3 = ss[wslot][j + 3];
                float w0 = swt[wslot][head][j],     w1 = swt[wslot][head][j + 1];
                float w2 = swt[wslot][head][j + 2], w3 = swt[wslot][head][j + 3];
                uint4 v0 = hh[(size_t)s0 * 32 + lane];
                uint4 v1 = hh[(size_t)s1 * 32 + lane];
                uint4 v2 = hh[(size_t)s2 * 32 + lane];
                uint4 v3 = hh[(size_t)s3 * 32 + lane];
                den += (w0 + w1) + (w2 + w3);
                fma_half8(acc0, v0, w0);
                fma_half8(acc1, v1, w1);
                fma_half8(acc0, v2, w2);
                fma_half8(acc1, v3, w3);
            }
            for (; j < nn; j++) {
                int s0 = ss[wslot][j];
                float w0 = swt[wslot][head][j];
                uint4 v0 = hh[(size_t)s0 * 32 + lane];
                den += w0;
                fma_half8(acc0, v0, w0);
            }
            __syncwarp();
        }
    }

    float inv = 1.f / (den + 1e-16f);
    float r[8];
    #pragma unroll
    for (int k = 0; k < 8; k++) r[k] = (acc0[k] + acc1[k]) * inv;
    #pragma unroll
    for (int k = 0; k < 8; ++k) {
        r[k] += __shfl_xor_sync(0xFFFFFFFFu, r[k], 8);
        r[k] += __shfl_xor_sync(0xFFFFFFFFu, r[k], 16);
    }
    if (lane < 8) {
        float o_[8];
        __half h8[8];
        #pragma unroll
        for (int k = 0; k < 8; ++k) {
            float v = 0.25f * r[k] + bias[lane * 8 + k];
            float sg = 1.f / (1.f + expf(-v));
            o_[k] = sg;
            h8[k] = __float2half(sg);
        }
        float4* op = (float4*)(out + (size_t)gw * 64 + lane * 8);
        op[0] = make_float4(o_[0], o_[1], o_[2], o_[3]);
        op[1] = make_float4(o_[4], o_[5], o_[6], o_[7]);
        out16[(size_t)gw * 8 + lane] = *(uint4*)h8;
    }
}

// ---------------- gate via wmma ----------------
__global__ void __launch_bounds__(128) gate_wmma_kernel(const __half* __restrict__ A,
                                                        const __half* __restrict__ B,
                                                        const float* __restrict__ gb1,
                                                        const float* __restrict__ gamma,
                                                        const float* __restrict__ beta,
                                                        const float* __restrict__ gw2,
                                                        const float* __restrict__ gb2,
                                                        float* __restrict__ gout, int N) {
    __shared__ float Cs[64 * 68];
    int tid = threadIdx.x;
    int warp = tid >> 5;
    int by = blockIdx.x;
    int row0 = by * 64 + warp * 16;

    wmma::fragment<wmma::accumulator, 16, 16, 16, float> cf[4];
    #pragma unroll
    for (int n = 0; n < 4; n++) wmma::fill_fragment(cf[n], 0.f);
    for (int k0 = 0; k0 < 64; k0 += 16) {
        wmma::fragment<wmma::matrix_a, 16, 16, 16, __half, wmma::row_major> af;
        wmma::load_matrix_sync(af, A + (size_t)row0 * 64 + k0, 64);
        #pragma unroll
        for (int n = 0; n < 4; n++) {
            wmma::fragment<wmma::matrix_b, 16, 16, 16, __half, wmma::row_major> bf;
            wmma::load_matrix_sync(bf, B + (size_t)k0 * 64 + n * 16, 64);
            wmma::mma_sync(cf[n], af, bf, cf[n]);
        }
    }
    #pragma unroll
    for (int n = 0; n < 4; n++)
        wmma::store_matrix_sync(Cs + warp * 16 * 68 + n * 16, cf[n], 68, wmma::mem_row_major);
    __syncthreads();

    int r = tid >> 1;
    int ch = (tid & 1) * 32;
    int row = by * 64 + r;
    float kinv = rsqrtf(1.0f + 1e-5f);
    float s = 0.f;
    #pragma unroll
    for (int c = 0; c < 32; c++) {
        float t = (Cs[r * 68 + ch + c] + __ldg(gb1 + ch + c)) * kinv * __ldg(gamma + ch + c)
                  + __ldg(beta + ch + c);
        t = fmaxf(t, 0.f);
        s += t * __ldg(gw2 + ch + c);
    }
    s += __shfl_xor_sync(0xFFFFFFFFu, s, 1);
    if ((tid & 1) == 0 && row < N) gout[row] = s + gb2[0];
}

// ---------------- per-graph boundaries (batch sorted) ----------------
__global__ void gptr_kernel(int N) {
    int v = blockIdx.x * blockDim.x + threadIdx.x;
    if (v >= N) return;
    int b = g_batch[v];
    if (v == 0) {
        for (int i = 0; i <= b; i++) g_gptr[i] = 0;
    } else {
        int bp = g_batch[v - 1];
        for (int i = bp + 1; i <= b; i++) g_gptr[i] = v;
    }
    if (v == N - 1) {
        for (int i = b + 1; i <= GNUM; i++) g_gptr[i] = N;
    }
}

// ---------------- pooling + final, fused ----------------
__global__ void __launch_bounds__(256) pool_kernel(const float* __restrict__ out2,
                                                   const float* __restrict__ lw,
                                                   const float* __restrict__ lb,
                                                   float* __restrict__ result, int N) {
    int b = blockIdx.x;
    int start = g_gptr[b], end = g_gptr[b + 1];
    __shared__ float smax[256];
    __shared__ float sacc[256];
    __shared__ float sden[4];
    int tid = threadIdx.x;
    float m = -1e30f;
    for (int v = start + tid; v < end; v += 256) m = fmaxf(m, g_gate[v]);
    smax[tid] = m;
    __syncthreads();
    for (int s = 128; s; s >>= 1) {
        if (tid < s) smax[tid] = fmaxf(smax[tid], smax[tid + s]);
        __syncthreads();
    }
    float mx = smax[0];
    __syncthreads();
    int c = tid & 63;
    int sub = tid >> 6;
    float acc = 0.f, dacc = 0.f;
    for (int v = start + sub; v < end; v += 4) {
        float w = expf(g_gate[v] - mx);
        acc += w * out2[(size_t)v * 64 + c];
        if (c == 0) dacc += w;
    }
    sacc[tid] = acc;
    if (c == 0) sden[sub] = dacc;
    __syncthreads();
    if (sub == 0) {
        float p = sacc[c] + sacc[64 + c] + sacc[128 + c] + sacc[192 + c];
        sacc[c] = p * __ldg(lw + c);
    }
    __syncthreads();
    if (tid < 32) {
        float t = sacc[tid] + sacc[tid + 32];
        #pragma unroll
        for (int o = 16; o; o >>= 1) t += __shfl_xor_sync(0xFFFFFFFFu, t, o);
        if (tid == 0) {
            float dt = sden[0] + sden[1] + sden[2] + sden[3];
            float s = t / (dt + 1e-16f) + lb[0];
            result[b] = 1.f / (1.f + expf(-s));
        }
    }
}

// ---------------- launch ----------------
extern "C" void kernel_launch(void* const* d_in, const int* in_sizes, int n_in,
                              void* d_out, int out_size) {
    const float* x  = (const float*)d_in[0];
    const void*  ei = d_in[1];
    const void*  bt = d_in[2];
    int o = (in_sizes[3] == 1) ? 1 : 0;
    const float* W1  = (const float*)d_in[3 + o];
    const float* as1 = (const float*)d_in[4 + o];
    const float* ad1 = (const float*)d_in[5 + o];
    const float* b1  = (const float*)d_in[6 + o];
    const float* W2  = (const float*)d_in[7 + o];
    const float* as2 = (const float*)d_in[8 + o];
    const float* ad2 = (const float*)d_in[9 + o];
    const float* b2  = (const float*)d_in[10 + o];
    const float* gw1 = (const float*)d_in[11 + o];
    const float* gb1 = (const float*)d_in[12 + o];
    const float* gam = (const float*)d_in[13 + o];
    const float* bet = (const float*)d_in[14 + o];
    const float* gw2 = (const float*)d_in[15 + o];
    const float* gb2 = (const float*)d_in[16 + o];
    const float* lw  = (const float*)d_in[17 + o];
    const float* lb  = (const float*)d_in[18 + o];

    int N = in_sizes[0] / 128;
    int E = in_sizes[1] / 2;

    __half *x16b, *w1hb, *w2hb, *gw1hb, *o16b;
    uint4* hhbuf;
    float *asrcb, *adstb, *out1b, *out2b, *gateb;
    cudaGetSymbolAddress((void**)&x16b,  g_x16);
    cudaGetSymbolAddress((void**)&w1hb,  g_w1h);
    cudaGetSymbolAddress((void**)&w2hb,  g_w2h);
    cudaGetSymbolAddress((void**)&gw1hb, g_gw1h);
    cudaGetSymbolAddress((void**)&o16b,  g_o16);
    cudaGetSymbolAddress((void**)&hhbuf, g_hh);
    cudaGetSymbolAddress((void**)&asrcb, g_asrc);
    cudaGetSymbolAddress((void**)&adstb, g_adst);
    cudaGetSymbolAddress((void**)&out1b, g_out1);
    cudaGetSymbolAddress((void**)&out2b, g_out2);
    cudaGetSymbolAddress((void**)&gateb, g_gate);

    int x8 = N * 128 / 8;
    int prepT = (x8 > 128 * 256) ? x8 : 128 * 256;

    // 0: prep
    prep_kernel<<<(prepT + 255) / 256, 256>>>((const long long*)ei, x, W1, W2, gw1, N, x8);
    // 1: convert
    int convT = 2 * E + N;
    convert_kernel<<<(convT + 255) / 256, 256>>>(ei, bt, E, N);
    // 2: fused CSR
    csr_kernel<<<CSRB, 256>>>(N, E);
    // 3: layer-1 GEMM (profiled slot)
    gemm_attn_kernel<<<NPAD / 64, 256>>>(x16b, w1hb, hhbuf, as1, ad1, asrcb, adstb, 128);
    // 4: layer-1 aggregate
    int wblocks = (N + 7) / 8;
    aggregate_kernel<<<wblocks, 256>>>(hhbuf, asrcb, adstb, b1, out1b, (uint4*)o16b, N);
    // 5-6: layer 2
    gemm_attn_kernel<<<NPAD / 64, 256>>>(o16b, w2hb, hhbuf, as2, ad2, asrcb, adstb, 64);
    aggregate_kernel<<<wblocks, 256>>>(hhbuf, asrcb, adstb, b2, out2b, (uint4*)o16b, N);
    // 7-9: gate, boundaries, pool+final
    gate_wmma_kernel<<<NPAD / 64, 128>>>(o16b, gw1hb, gb1, gam, bet, gw2, gb2, gateb, N);
    gptr_kernel<<<(N + 255) / 256, 256>>>(N);
    pool_kernel<<<GNUM, 256>>>(out2b, lw, lb, (float*)d_out, N);
}